// round 15
// baseline (speedup 1.0000x reference)
#include <cuda_runtime.h>
#include <cuda_fp16.h>
#include <cstdint>

// ---------------- problem constants ----------------
#define BATCH 64
#define SEQ 197
#define NPATCH 196
#define DIM 768
#define NHEAD 12
#define DH 64
#define MLPD 3072
#define OUTD 1000
#define NLAYER 12
#define ALD 224                 // padded attention K length (mult of 32)

// ---------------- scratch (static device globals; no allocation) ----------------
__device__ float g_out[(long long)BATCH * SEQ * DIM];          // residual stream
__device__ float g_ptmp[(long long)BATCH * NPATCH * DIM];      // patch-embed fp32 out

// fp16 activation / weight buffers
__device__ __half g_ph[(long long)BATCH * NPATCH * DIM];   // patches
__device__ __half g_xh[(long long)BATCH * SEQ * DIM];      // ln out
__device__ __half g_mh[(long long)BATCH * SEQ * MLPD];     // mlp hidden
__device__ __half g_qh[(long long)BATCH * SEQ * DIM];
__device__ __half g_kh[(long long)BATCH * SEQ * DIM];
__device__ __half g_vth[(long long)BATCH * NHEAD * DH * ALD];  // V^T [n][h][o][s-pad]
__device__ __half g_wph[(long long)DIM * DIM];
__device__ __half g_w1h[(long long)NLAYER * MLPD * DIM];
__device__ __half g_w2h[(long long)NLAYER * DIM * MLPD];
__device__ __half g_wqkv[(long long)NLAYER * NHEAD * 192 * DH]; // packed Q|K|V per head
__device__ float  g_bqkv[(long long)NLAYER * NHEAD * 192];

// ---------------- helpers ----------------
__device__ __forceinline__ uint32_t smem_u32(const void* p) {
    uint32_t a;
    asm("{ .reg .u64 t; cvta.to.shared.u64 t, %1; cvt.u32.u64 %0, t; }" : "=r"(a) : "l"(p));
    return a;
}

__device__ __forceinline__ void ldm4(uint32_t* r, uint32_t addr) {
    asm volatile("ldmatrix.sync.aligned.m8n8.x4.shared.b16 {%0,%1,%2,%3}, [%4];"
                 : "=r"(r[0]), "=r"(r[1]), "=r"(r[2]), "=r"(r[3]) : "r"(addr));
}

__device__ __forceinline__ void mma_fp16(float* c, const uint32_t* a, uint32_t b0, uint32_t b1) {
    asm volatile(
        "mma.sync.aligned.m16n8k16.row.col.f32.f16.f16.f32 "
        "{%0,%1,%2,%3}, {%4,%5,%6,%7}, {%8,%9}, {%0,%1,%2,%3};"
        : "+f"(c[0]), "+f"(c[1]), "+f"(c[2]), "+f"(c[3])
        : "r"(a[0]), "r"(a[1]), "r"(a[2]), "r"(a[3]), "r"(b0), "r"(b1));
}

__device__ __forceinline__ uint32_t pack_h2(float lo, float hi) {
    __half2 h = __floats2half2_rn(lo, hi);
    return *(uint32_t*)&h;
}

// exact-GELU via Abramowitz-Stegun 7.1.26 erf approximation (|erf err| <= 1.5e-7,
// far below the fp16 rounding the result immediately undergoes)
__device__ __forceinline__ float fast_gelu(float x) {
    float z = fabsf(x) * 0.70710678118654752f;
    float t = __frcp_rn(1.0f + 0.3275911f * z);
    float poly = t * (0.254829592f + t * (-0.284496736f + t * (1.421413741f +
                 t * (-1.453152027f + t * 1.061405429f))));
    float erfv = 1.0f - poly * __expf(-z * z);
    erfv = copysignf(erfv, x);
    return 0.5f * x * (1.0f + erfv);
}

__device__ __forceinline__ void cp_async16(uint32_t dst, const void* src, int valid) {
    asm volatile("cp.async.cg.shared.global [%0], [%1], 16, %2;"
                 :: "r"(dst), "l"(src), "r"(valid));
}
__device__ __forceinline__ void cp_commit() { asm volatile("cp.async.commit_group;"); }
__device__ __forceinline__ void cp_wait1() { asm volatile("cp.async.wait_group 1;"); }
__device__ __forceinline__ void cp_wait0() { asm volatile("cp.async.wait_group 0;"); }

// ======================================================================
//  fp16 batched NT GEMM: 128x128 CTA tile, 8 warps (64x32 warp tile)
//  modes: 0 = fp32 out (+R), 1 = fp16 out, 2 = QKV routing (q/k/vT)
//  ksplit>1: blockIdx.z = K-split index, epilogue atomicAdd into Cf
// ======================================================================
#define RSB 80
#define PLB (128 * RSB)
#define STB (2 * PLB)
#define NSTAGE 3
#define SMEM_MMA (NSTAGE * STB)

__global__ __launch_bounds__(256, 2)
void gemm_fp16_kernel(const __half* __restrict__ Ah, long long lda, long long sA1, long long sA2,
                      const __half* __restrict__ Bh, long long ldb, long long sB1, long long sB2,
                      float* __restrict__ Cf, __half* __restrict__ Ch,
                      long long ldc, long long sC1, long long sC2,
                      const float* __restrict__ bias, long long sb1, long long sb2,
                      const float* __restrict__ R,
                      __half* __restrict__ Kout, __half* __restrict__ Vout,
                      int M, int N, int K, int gelu, int z2, int mode, int seq, int ksplit)
{
    extern __shared__ char sm[];
    uint32_t smb = smem_u32(sm);
    const int tid = threadIdx.x;
    const int lid = tid & 31;
    const int wid = tid >> 5;
    const int wm = wid >> 2;          // 0..1
    const int wn = wid & 3;           // 0..3
    const int m0 = blockIdx.y * 128;
    const int n0 = blockIdx.x * 128;
    int head = 0;
    int split = 0;
    int kbase = 0;
    int Kloc = K;

    if (ksplit > 1) {
        split = blockIdx.z;
        Kloc = K / ksplit;
        kbase = split * Kloc;
    } else {
        int bz = blockIdx.z;
        int i1 = bz / z2, i2 = bz % z2;
        head = i2;
        Ah += i1 * sA1 + i2 * sA2;
        Bh += i1 * sB1 + i2 * sB2;
        if (Cf) Cf += i1 * sC1 + i2 * sC2;
        if (Ch && mode != 2) Ch += i1 * sC1 + i2 * sC2;
        if (bias) bias += i1 * sb1 + i2 * sb2;
    }

    const int nch = Kloc >> 5;

    auto load_stage = [&](int s, int chunk) {
        int k0 = kbase + (chunk << 5);
        uint32_t sbase = smb + s * STB;
        #pragma unroll
        for (int t = 0; t < 4; t++) {
            int id = tid + t * 256;
            int plane = id >> 9;
            int rc = id & 511;
            int row = rc >> 2;
            int c = rc & 3;
            uint32_t dst = sbase + plane * PLB + row * RSB + c * 16;
            const __half* src;
            int valid;
            if (plane == 0) {
                int gm = m0 + row;
                int gmc = gm < M ? gm : M - 1;
                src = Ah + (long long)gmc * lda + k0 + c * 8;
                valid = (gm < M) ? 16 : 0;
            } else {
                int gn = n0 + row;
                int gnc = gn < N ? gn : N - 1;
                src = Bh + (long long)gnc * ldb + k0 + c * 8;
                valid = (gn < N) ? 16 : 0;
            }
            cp_async16(dst, src, valid);
        }
        cp_commit();
    };

    float acc[4][4][4];
    #pragma unroll
    for (int i = 0; i < 4; i++)
        #pragma unroll
        for (int j = 0; j < 4; j++)
            #pragma unroll
            for (int r = 0; r < 4; r++) acc[i][j][r] = 0.f;

    load_stage(0, 0);
    if (nch > 1) load_stage(1, 1);

    for (int i = 0; i < nch; i++) {
        if (i == nch - 1) cp_wait0(); else cp_wait1();
        __syncthreads();
        if (i + 2 < nch) load_stage((i + 2) % NSTAGE, i + 2);

        uint32_t sA = smb + (i % NSTAGE) * STB;
        uint32_t sB = sA + PLB;
        #pragma unroll
        for (int kk = 0; kk < 2; kk++) {
            int kt = kk << 4;
            uint32_t af[4][4];
            #pragma unroll
            for (int t = 0; t < 4; t++) {
                int m = wm * 64 + t * 16;
                uint32_t row = m + ((lid >> 3) & 1) * 8 + (lid & 7);
                uint32_t koff = kt + (lid >> 4) * 8;
                ldm4(af[t], sA + row * RSB + koff * 2);
            }
            uint32_t bf[2][4];
            #pragma unroll
            for (int p = 0; p < 2; p++) {
                int n = wn * 32 + p * 16;
                uint32_t row = n + (lid >> 4) * 8 + (lid & 7);
                uint32_t koff = kt + ((lid >> 3) & 1) * 8;
                ldm4(bf[p], sB + row * RSB + koff * 2);
            }
            #pragma unroll
            for (int t = 0; t < 4; t++) {
                #pragma unroll
                for (int j = 0; j < 4; j++) {
                    uint32_t b0 = bf[j >> 1][(j & 1) * 2], b1 = bf[j >> 1][(j & 1) * 2 + 1];
                    mma_fp16(acc[t][j], af[t], b0, b1);
                }
            }
        }
        __syncthreads();
    }

    // ---- epilogue ----
    #pragma unroll
    for (int t = 0; t < 4; t++) {
        #pragma unroll
        for (int j = 0; j < 4; j++) {
            int col = n0 + wn * 32 + j * 8 + (lid & 3) * 2;
            #pragma unroll
            for (int h = 0; h < 2; h++) {
                int row = m0 + wm * 64 + t * 16 + (lid >> 2) + h * 8;
                if (row >= M) continue;
                #pragma unroll
                for (int e = 0; e < 2; e++) {
                    int c = col + e;
                    if (c >= N) continue;
                    float v = acc[t][j][h * 2 + e];
                    if (bias && split == 0) v += bias[c];
                    if (gelu) v = fast_gelu(v);
                    if (mode == 0) {
                        long long base = (long long)row * ldc + c;
                        if (ksplit > 1) {
                            atomicAdd(&Cf[base], v);
                        } else {
                            float r = R ? R[base] : 0.f;
                            Cf[base] = v + r;
                        }
                    } else if (mode == 1) {
                        Ch[(long long)row * ldc + c] = __float2half_rn(v);
                    } else {
                        // QKV routing: c<64 -> q, c<128 -> k, else -> vT (SEQ compile-time)
                        __half hv = __float2half_rn(v);
                        if (c < 64) {
                            Ch[(long long)row * DIM + head * DH + c] = hv;
                        } else if (c < 128) {
                            Kout[(long long)row * DIM + head * DH + (c - 64)] = hv;
                        } else {
                            int nb = row / SEQ, s = row - nb * SEQ;
                            Vout[((long long)(nb * NHEAD + head) * DH + (c - 128)) * ALD + s] = hv;
                        }
                    }
                }
            }
        }
    }
}

// ======================================================================
//  fused flash attention: per (qtile, h, n) CTA
// ======================================================================
#define FA_RSQ 144
#define FA_RSV 464
#define FA_SM_Q 0
#define FA_SM_K (128 * FA_RSQ)
#define FA_SM_V (FA_SM_K + ALD * FA_RSQ)
#define FA_SMEM (FA_SM_V + DH * FA_RSV)

__global__ __launch_bounds__(256, 1)
void flash_kernel(const __half* __restrict__ qh, const __half* __restrict__ kh,
                  const __half* __restrict__ vth, float* __restrict__ outb)
{
    extern __shared__ char sm[];
    uint32_t smb = smem_u32(sm);
    const int tid = threadIdx.x;
    const int lid = tid & 31;
    const int wid = tid >> 5;
    const int q0 = blockIdx.x * 128;
    const int h  = blockIdx.y;
    const int n  = blockIdx.z;
    const int wr = wid * 16;

    const long long qbase = ((long long)n * SEQ) * DIM + h * DH;
    const long long vbase = ((long long)n * NHEAD + h) * (long long)DH * ALD;

    #pragma unroll
    for (int t = 0; t < 4; t++) {
        int id = tid + t * 256;
        int row = id >> 3, ch = id & 7;
        int s = q0 + row; if (s >= SEQ) s = SEQ - 1;
        *(uint4*)(sm + FA_SM_Q + row * FA_RSQ + ch * 16) =
            *(const uint4*)(qh + qbase + (long long)s * DIM + ch * 8);
    }
    #pragma unroll
    for (int t = 0; t < 7; t++) {
        int id = tid + t * 256;
        int row = id >> 3, ch = id & 7;
        int s = row; if (s >= SEQ) s = SEQ - 1;
        *(uint4*)(sm + FA_SM_K + row * FA_RSQ + ch * 16) =
            *(const uint4*)(kh + qbase + (long long)s * DIM + ch * 8);
    }
    for (int id = tid; id < DH * 28; id += 256) {
        int row = id / 28, ch = id % 28;
        *(uint4*)(sm + FA_SM_V + row * FA_RSV + ch * 16) =
            *(const uint4*)(vth + vbase + (long long)row * ALD + ch * 8);
    }
    __syncthreads();

    uint32_t aq[4][4];
    #pragma unroll
    for (int kt = 0; kt < 4; kt++) {
        uint32_t row = wr + ((lid >> 3) & 1) * 8 + (lid & 7);
        uint32_t koff = kt * 16 + (lid >> 4) * 8;
        ldm4(aq[kt], smb + FA_SM_Q + row * FA_RSQ + koff * 2);
    }
    float acc[28][4];
    #pragma unroll
    for (int j = 0; j < 28; j++)
        #pragma unroll
        for (int r = 0; r < 4; r++) acc[j][r] = 0.f;

    #pragma unroll
    for (int nt = 0; nt < 14; nt++) {
        #pragma unroll
        for (int kt = 0; kt < 4; kt++) {
            uint32_t bk[4];
            uint32_t row = nt * 16 + (lid >> 4) * 8 + (lid & 7);
            uint32_t koff = kt * 16 + ((lid >> 3) & 1) * 8;
            ldm4(bk, smb + FA_SM_K + row * FA_RSQ + koff * 2);
            mma_fp16(acc[nt * 2],     aq[kt], bk[0], bk[1]);
            mma_fp16(acc[nt * 2 + 1], aq[kt], bk[2], bk[3]);
        }
    }

    float m0 = -1e30f, m1 = -1e30f;
    #pragma unroll
    for (int j = 0; j < 28; j++) {
        int c0 = j * 8 + (lid & 3) * 2;
        if (c0 >= SEQ)     { acc[j][0] = -1e30f; acc[j][2] = -1e30f; }
        if (c0 + 1 >= SEQ) { acc[j][1] = -1e30f; acc[j][3] = -1e30f; }
        m0 = fmaxf(m0, fmaxf(acc[j][0], acc[j][1]));
        m1 = fmaxf(m1, fmaxf(acc[j][2], acc[j][3]));
    }
    m0 = fmaxf(m0, __shfl_xor_sync(0xffffffffu, m0, 1));
    m0 = fmaxf(m0, __shfl_xor_sync(0xffffffffu, m0, 2));
    m1 = fmaxf(m1, __shfl_xor_sync(0xffffffffu, m1, 1));
    m1 = fmaxf(m1, __shfl_xor_sync(0xffffffffu, m1, 2));

    float s0 = 0.f, s1 = 0.f;
    #pragma unroll
    for (int j = 0; j < 28; j++) {
        acc[j][0] = __expf((acc[j][0] - m0) * 0.125f);
        acc[j][1] = __expf((acc[j][1] - m0) * 0.125f);
        acc[j][2] = __expf((acc[j][2] - m1) * 0.125f);
        acc[j][3] = __expf((acc[j][3] - m1) * 0.125f);
        s0 += acc[j][0] + acc[j][1];
        s1 += acc[j][2] + acc[j][3];
    }
    s0 += __shfl_xor_sync(0xffffffffu, s0, 1);
    s0 += __shfl_xor_sync(0xffffffffu, s0, 2);
    s1 += __shfl_xor_sync(0xffffffffu, s1, 1);
    s1 += __shfl_xor_sync(0xffffffffu, s1, 2);
    float inv0 = 1.0f / s0, inv1 = 1.0f / s1;

    float o[8][4];
    #pragma unroll
    for (int g = 0; g < 8; g++)
        #pragma unroll
        for (int r = 0; r < 4; r++) o[g][r] = 0.f;

    #pragma unroll
    for (int kt2 = 0; kt2 < 14; kt2++) {
        int j0 = kt2 * 2, j1 = j0 + 1;
        uint32_t af[4];
        af[0] = pack_h2(acc[j0][0], acc[j0][1]);
        af[1] = pack_h2(acc[j0][2], acc[j0][3]);
        af[2] = pack_h2(acc[j1][0], acc[j1][1]);
        af[3] = pack_h2(acc[j1][2], acc[j1][3]);
        #pragma unroll
        for (int g = 0; g < 4; g++) {
            uint32_t bv[4];
            uint32_t row = g * 16 + (lid >> 4) * 8 + (lid & 7);
            uint32_t koff = kt2 * 16 + ((lid >> 3) & 1) * 8;
            ldm4(bv, smb + FA_SM_V + row * FA_RSV + koff * 2);
            mma_fp16(o[g * 2],     af, bv[0], bv[1]);
            mma_fp16(o[g * 2 + 1], af, bv[2], bv[3]);
        }
    }

    int r0 = q0 + wr + (lid >> 2);
    int r1 = r0 + 8;
    #pragma unroll
    for (int g = 0; g < 8; g++) {
        int c = h * DH + g * 8 + (lid & 3) * 2;
        if (r0 < SEQ) {
            long long b = ((long long)n * SEQ + r0) * DIM + c;
            outb[b]     += o[g][0] * inv0;
            outb[b + 1] += o[g][1] * inv0;
        }
        if (r1 < SEQ) {
            long long b = ((long long)n * SEQ + r1) * DIM + c;
            outb[b]     += o[g][2] * inv1;
            outb[b + 1] += o[g][3] * inv1;
        }
    }
}

// ======================================================================
//  small kernels
// ======================================================================
__global__ void zero_fp16_kernel(__half* __restrict__ p, long long n) {
    long long i = ((long long)blockIdx.x * 256 + threadIdx.x) * 8;
    if (i >= n) return;
    *(uint4*)(p + i) = make_uint4(0, 0, 0, 0);
}

// fp32 -> fp16, 8 elements per thread
__global__ void cvt_kernel(const float* __restrict__ x, __half* __restrict__ h, long long n) {
    long long i = ((long long)blockIdx.x * 256 + threadIdx.x) * 8;
    if (i >= n) return;
    float4 a = *(const float4*)(x + i);
    float4 b = *(const float4*)(x + i + 4);
    uint4 o;
    o.x = pack_h2(a.x, a.y);
    o.y = pack_h2(a.z, a.w);
    o.z = pack_h2(b.x, b.y);
    o.w = pack_h2(b.z, b.w);
    *(uint4*)(h + i) = o;
}

// pack Wq/Wk/Wv [L][H][64][64] fp32 -> wqkv [L][H][192][64] fp16
__global__ void pack_qkv_w_kernel(const float* __restrict__ Wq, const float* __restrict__ Wk,
                                  const float* __restrict__ Wv, __half* __restrict__ out) {
    long long idx = (long long)blockIdx.x * 256 + threadIdx.x;
    const long long total = (long long)NLAYER * NHEAD * 192 * DH;
    if (idx >= total) return;
    int c = (int)(idx & 63);
    long long t = idx >> 6;
    int r = (int)(t % 192);
    long long lh = t / 192;
    const float* src = (r < 64) ? Wq : (r < 128 ? Wk : Wv);
    int rr = r & 63;
    out[idx] = __float2half_rn(src[(lh * 64 + rr) * 64 + c]);
}

// pack bq/bk/bv [L][H][64] fp32 -> bqkv [L][H][192] fp32
__global__ void pack_qkv_b_kernel(const float* __restrict__ bq, const float* __restrict__ bk,
                                  const float* __restrict__ bv, float* __restrict__ out) {
    long long idx = (long long)blockIdx.x * 256 + threadIdx.x;
    const long long total = (long long)NLAYER * NHEAD * 192;
    if (idx >= total) return;
    int r = (int)(idx % 192);
    long long lh = idx / 192;
    const float* src = (r < 64) ? bq : (r < 128 ? bk : bv);
    out[idx] = src[lh * 64 + (r & 63)];
}

__global__ void patchify_kernel(const float* __restrict__ x, __half* __restrict__ ph) {
    long long idx = (long long)blockIdx.x * 256 + threadIdx.x;
    const long long total = (long long)BATCH * NPATCH * DIM;
    if (idx >= total) return;
    int e = (int)(idx % DIM);
    long long r = idx / DIM;
    int p = (int)(r % NPATCH);
    int n = (int)(r / NPATCH);
    int c = e / 256;
    int hw = e % 256;
    int hi = hw / 16, wi = hw % 16;
    int pi = p / 14, pj = p % 14;
    ph[idx] = __float2half_rn(
        x[(((long long)n * 3 + c) * 224 + (pi * 16 + hi)) * 224 + (pj * 16 + wi)]);
}

__global__ void assemble_kernel(const float* __restrict__ tmp, const float* __restrict__ cls,
                                float* __restrict__ out) {
    long long idx = (long long)blockIdx.x * 256 + threadIdx.x;
    const long long total = (long long)BATCH * SEQ * DIM;
    if (idx >= total) return;
    int d = (int)(idx % DIM);
    long long r = idx / DIM;
    int s = (int)(r % SEQ);
    int n = (int)(r / SEQ);
    float v = (s == 0) ? cls[d] : tmp[((long long)n * NPATCH + (s - 1)) * DIM + d];
    float pe;
    if ((s & 1) == 0) pe = sinf((float)s / powf(10000.0f, (float)d / (float)DIM));
    else              pe = cosf((float)s / powf(10000.0f, (float)(d - 1) / (float)DIM));
    out[idx] = v + pe;
}

// warp-per-row layernorm: 8 rows per 256-thread block, shuffle-only reduction
__global__ __launch_bounds__(256)
void layernorm_kernel(const float* __restrict__ x, const float* __restrict__ g,
                      const float* __restrict__ b, __half* __restrict__ yh) {
    int warp = threadIdx.x >> 5;
    int lid = threadIdx.x & 31;
    long long row = (long long)blockIdx.x * 8 + warp;
    const float4* p = (const float4*)(x + row * DIM);
    const float4* gv = (const float4*)g;
    const float4* bv = (const float4*)b;

    float4 v[6];
    float s = 0.f, s2 = 0.f;
    #pragma unroll
    for (int k = 0; k < 6; k++) {
        v[k] = p[lid + k * 32];
        s  += v[k].x + v[k].y + v[k].z + v[k].w;
        s2 += v[k].x * v[k].x + v[k].y * v[k].y + v[k].z * v[k].z + v[k].w * v[k].w;
    }
    #pragma unroll
    for (int o = 16; o > 0; o >>= 1) {
        s  += __shfl_xor_sync(0xffffffffu, s, o);
        s2 += __shfl_xor_sync(0xffffffffu, s2, o);
    }
    float mu = s * (1.0f / DIM);
    float var = s2 * (1.0f / DIM) - mu * mu;
    float inv = rsqrtf(var + 1e-5f);

    uint2* out = (uint2*)(yh + row * DIM);
    #pragma unroll
    for (int k = 0; k < 6; k++) {
        float4 gg = gv[lid + k * 32];
        float4 bb = bv[lid + k * 32];
        float r0 = (v[k].x - mu) * inv * gg.x + bb.x;
        float r1 = (v[k].y - mu) * inv * gg.y + bb.y;
        float r2 = (v[k].z - mu) * inv * gg.z + bb.z;
        float r3 = (v[k].w - mu) * inv * gg.w + bb.w;
        uint2 o;
        o.x = pack_h2(r0, r1);
        o.y = pack_h2(r2, r3);
        out[lid + k * 32] = o;
    }
}

// ======================================================================
//  generic SIMT GEMM (head only)
// ======================================================================
#define BM 64
#define BN 64
#define BK 16

__global__ void gemm_simt_kernel(
    const float* __restrict__ A, int lda,
    const float* __restrict__ B, int ldb,
    float* __restrict__ C, int ldc,
    const float* __restrict__ bias,
    int M, int N, int K)
{
    __shared__ float As[BK][BM];
    __shared__ float Bs[BK][BN];
    int bm = blockIdx.y * BM;
    int bn = blockIdx.x * BN;
    int tid = threadIdx.x;
    int tx = tid % 16, ty = tid / 16;
    float acc[4][4] = {};
    for (int k0 = 0; k0 < K; k0 += BK) {
        #pragma unroll
        for (int i = 0; i < 4; i++) {
            int idx = tid + i * 256;
            int m = idx / BK, kk = idx % BK;
            int gm = bm + m, gk = k0 + kk;
            As[kk][m] = (gm < M && gk < K) ? A[(long long)gm * lda + gk] : 0.f;
        }
        #pragma unroll
        for (int i = 0; i < 4; i++) {
            int idx = tid + i * 256;
            int n = idx / BK, kk = idx % BK;
            int gn = bn + n, gk = k0 + kk;
            Bs[kk][n] = (gn < N && gk < K) ? B[(long long)gn * ldb + gk] : 0.f;
        }
        __syncthreads();
        #pragma unroll
        for (int kk = 0; kk < BK; kk++) {
            float a[4], b[4];
            #pragma unroll
            for (int i = 0; i < 4; i++) a[i] = As[kk][ty * 4 + i];
            #pragma unroll
            for (int j = 0; j < 4; j++) b[j] = Bs[kk][tx * 4 + j];
            #pragma unroll
            for (int i = 0; i < 4; i++)
                #pragma unroll
                for (int j = 0; j < 4; j++)
                    acc[i][j] += a[i] * b[j];
        }
        __syncthreads();
    }
    #pragma unroll
    for (int i = 0; i < 4; i++) {
        int gm = bm + ty * 4 + i;
        if (gm >= M) continue;
        #pragma unroll
        for (int j = 0; j < 4; j++) {
            int gn = bn + tx * 4 + j;
            if (gn >= N) continue;
            C[(long long)gm * ldc + gn] = acc[i][j] + (bias ? bias[gn] : 0.f);
        }
    }
}

// ======================================================================
//  launch helper
// ======================================================================
struct MArgs {
    const __half *Ah; long long lda, sA1, sA2;
    const __half *Bh; long long ldb, sB1, sB2;
    float* Cf; __half* Ch; long long ldc, sC1, sC2;
    const float* bias; long long sb1, sb2;
    const float* R;
    __half *Kout, *Vout;
    int M, N, K; int gelu; int z2; int Z; int mode; int ksplit;
};

static void launch_mma(const MArgs& a, cudaStream_t stream) {
    static bool attr_set = false;
    if (!attr_set) {
        cudaFuncSetAttribute(gemm_fp16_kernel,
                             cudaFuncAttributeMaxDynamicSharedMemorySize, SMEM_MMA);
        cudaFuncSetAttribute(flash_kernel,
                             cudaFuncAttributeMaxDynamicSharedMemorySize, FA_SMEM);
        attr_set = true;
    }
    int zdim = (a.ksplit > 1) ? a.ksplit : a.Z;
    dim3 grid((a.N + 127) / 128, (a.M + 127) / 128, zdim);
    gemm_fp16_kernel<<<grid, 256, SMEM_MMA, stream>>>(
        a.Ah, a.lda, a.sA1, a.sA2,
        a.Bh, a.ldb, a.sB1, a.sB2,
        a.Cf, a.Ch, a.ldc, a.sC1, a.sC2,
        a.bias, a.sb1, a.sb2, a.R, a.Kout, a.Vout,
        a.M, a.N, a.K, a.gelu, a.z2, a.mode, SEQ, a.ksplit);
}

// ======================================================================
//  orchestration (single stream)
// ======================================================================
extern "C" void kernel_launch(void* const* d_in, const int* in_sizes, int n_in,
                              void* d_out, int out_size) {
    (void)in_sizes; (void)n_in; (void)out_size;
    const float* x    = (const float*)d_in[0];
    const float* Wp   = (const float*)d_in[1];
    const float* bp   = (const float*)d_in[2];
    const float* cls  = (const float*)d_in[3];
    const float* ln1g = (const float*)d_in[4];
    const float* ln1b = (const float*)d_in[5];
    const float* Wq   = (const float*)d_in[6];
    const float* bq   = (const float*)d_in[7];
    const float* Wk   = (const float*)d_in[8];
    const float* bk   = (const float*)d_in[9];
    const float* Wv   = (const float*)d_in[10];
    const float* bv   = (const float*)d_in[11];
    const float* ln2g = (const float*)d_in[12];
    const float* ln2b = (const float*)d_in[13];
    const float* W1   = (const float*)d_in[14];
    const float* b1   = (const float*)d_in[15];
    const float* W2   = (const float*)d_in[16];
    const float* b2   = (const float*)d_in[17];
    const float* Wh   = (const float*)d_in[18];
    const float* bh   = (const float*)d_in[19];
    float* out_final  = (float*)d_out;

    float *outb, *ptmp, *bqkv;
    __half *ph, *xh, *mh, *qh, *kh, *vth;
    __half *wph, *w1h, *w2h, *wqkv;
    cudaGetSymbolAddress((void**)&outb, g_out);
    cudaGetSymbolAddress((void**)&ptmp, g_ptmp);
    cudaGetSymbolAddress((void**)&ph,   g_ph);
    cudaGetSymbolAddress((void**)&xh,   g_xh);
    cudaGetSymbolAddress((void**)&mh,   g_mh);
    cudaGetSymbolAddress((void**)&qh,   g_qh);
    cudaGetSymbolAddress((void**)&kh,   g_kh);
    cudaGetSymbolAddress((void**)&vth,  g_vth);
    cudaGetSymbolAddress((void**)&wph,  g_wph);
    cudaGetSymbolAddress((void**)&w1h,  g_w1h);
    cudaGetSymbolAddress((void**)&w2h,  g_w2h);
    cudaGetSymbolAddress((void**)&wqkv, g_wqkv);
    cudaGetSymbolAddress((void**)&bqkv, g_bqkv);

    cudaStream_t stream = 0;
    const int ROWS = BATCH * SEQ;                    // 12608

    // 0) weight converts + QKV pack + vT pad zero
    {
        long long n;
        n = (long long)DIM * DIM;
        cvt_kernel<<<(unsigned)((n / 8 + 255) / 256), 256, 0, stream>>>(Wp, wph, n);
        n = (long long)NLAYER * MLPD * DIM;
        cvt_kernel<<<(unsigned)((n / 8 + 255) / 256), 256, 0, stream>>>(W1, w1h, n);
        cvt_kernel<<<(unsigned)((n / 8 + 255) / 256), 256, 0, stream>>>(W2, w2h, n);
        n = (long long)NLAYER * NHEAD * 192 * DH;
        pack_qkv_w_kernel<<<(unsigned)((n + 255) / 256), 256, 0, stream>>>(Wq, Wk, Wv, wqkv);
        n = (long long)NLAYER * NHEAD * 192;
        pack_qkv_b_kernel<<<(unsigned)((n + 255) / 256), 256, 0, stream>>>(bq, bk, bv, bqkv);
        n = (long long)BATCH * NHEAD * DH * ALD;
        zero_fp16_kernel<<<(unsigned)((n / 8 + 255) / 256), 256, 0, stream>>>(vth, n);
    }

    // 1) patchify -> fp16
    {
        long long total = (long long)BATCH * NPATCH * DIM;
        patchify_kernel<<<(unsigned)((total + 255) / 256), 256, 0, stream>>>(x, ph);
    }
    // 2) patch embedding: ptmp = patches @ Wp^T + bp
    {
        MArgs a = {};
        a.Ah = ph; a.lda = DIM;
        a.Bh = wph; a.ldb = DIM;
        a.Cf = ptmp; a.ldc = DIM;
        a.bias = bp;
        a.M = BATCH * NPATCH; a.N = DIM; a.K = DIM;
        a.z2 = 1; a.Z = 1; a.mode = 0; a.ksplit = 1;
        launch_mma(a, stream);
    }
    // 3) assemble tokens + cls + positional embedding
    {
        long long total = (long long)BATCH * SEQ * DIM;
        assemble_kernel<<<(unsigned)((total + 255) / 256), 256, 0, stream>>>(ptmp, cls, outb);
    }

    for (int l = 0; l < NLAYER; l++) {
        // --- ln1 -> fp16 ---
        layernorm_kernel<<<ROWS / 8, 256, 0, stream>>>(outb, ln1g + l * DIM, ln1b + l * DIM, xh);

        // --- fused QKV projection (one launch, Z=12 heads, N=192) ---
        {
            MArgs a = {};
            a.Ah = xh; a.lda = DIM; a.sA2 = DH;
            a.Bh = wqkv + (long long)l * NHEAD * 192 * DH; a.ldb = DH; a.sB2 = 192 * DH;
            a.Ch = qh; a.Kout = kh; a.Vout = vth;
            a.bias = bqkv + (long long)l * NHEAD * 192; a.sb2 = 192;
            a.M = ROWS; a.N = 192; a.K = DH;
            a.z2 = NHEAD; a.Z = NHEAD; a.mode = 2; a.ksplit = 1;
            launch_mma(a, stream);
        }

        // --- fused attention + residual ---
        {
            dim3 grid(2, NHEAD, BATCH);
            flash_kernel<<<grid, 256, FA_SMEM, stream>>>(qh, kh, vth, outb);
        }

        // --- ln2 -> fp16 ---
        layernorm_kernel<<<ROWS / 8, 256, 0, stream>>>(outb, ln2g + l * DIM, ln2b + l * DIM, xh);

        // --- MLP1 + GELU -> fp16 ---
        {
            MArgs a = {};
            a.Ah = xh; a.lda = DIM;
            a.Bh = w1h + (long long)l * MLPD * DIM; a.ldb = DIM;
            a.Ch = mh; a.ldc = MLPD;
            a.bias = b1 + (long long)l * MLPD;
            a.M = ROWS; a.N = MLPD; a.K = DIM; a.gelu = 1;
            a.z2 = 1; a.Z = 1; a.mode = 1; a.ksplit = 1;
            launch_mma(a, stream);
        }
        // --- MLP2 + residual -> fp32, split-K=2 (atomicAdd onto outb) ---
        {
            MArgs a = {};
            a.Ah = mh; a.lda = MLPD;
            a.Bh = w2h + (long long)l * DIM * MLPD; a.ldb = MLPD;
            a.Cf = outb; a.ldc = DIM;
            a.bias = b2 + (long long)l * DIM;
            a.M = ROWS; a.N = DIM; a.K = MLPD;
            a.z2 = 1; a.Z = 1; a.mode = 0; a.ksplit = 2;
            launch_mma(a, stream);
        }
    }

    // --- head: out_final = out[:,0,:] @ Wh^T + bh (SIMT, tiny) ---
    {
        dim3 grid((OUTD + BN - 1) / BN, (BATCH + BM - 1) / BM, 1);
        gemm_simt_kernel<<<grid, 256, 0, stream>>>(
            outb, (int)((long long)SEQ * DIM), Wh, DIM, out_final, OUTD, bh, BATCH, OUTD, DIM);
    }
}

// round 16
// speedup vs baseline: 1.0289x; 1.0289x over previous
#include <cuda_runtime.h>
#include <cuda_fp16.h>
#include <cstdint>

// ---------------- problem constants ----------------
#define BATCH 64
#define SEQ 197
#define NPATCH 196
#define DIM 768
#define NHEAD 12
#define DH 64
#define MLPD 3072
#define OUTD 1000
#define NLAYER 12
#define ALD 224                 // padded attention K length (mult of 32)

// ---------------- scratch (static device globals; no allocation) ----------------
__device__ float g_out[(long long)BATCH * SEQ * DIM];          // residual stream
__device__ float g_ptmp[(long long)BATCH * NPATCH * DIM];      // patch-embed fp32 out

// fp16 activation / weight buffers
__device__ __half g_ph[(long long)BATCH * NPATCH * DIM];   // patches
__device__ __half g_xh[(long long)BATCH * SEQ * DIM];      // ln out
__device__ __half g_mh[(long long)BATCH * SEQ * MLPD];     // mlp hidden
__device__ __half g_qh[(long long)BATCH * SEQ * DIM];
__device__ __half g_kh[(long long)BATCH * SEQ * DIM];
__device__ __half g_vth[(long long)BATCH * NHEAD * DH * ALD];  // V^T [n][h][o][s-pad]
__device__ __half g_wph[(long long)DIM * DIM];
__device__ __half g_w1h[(long long)NLAYER * MLPD * DIM];
__device__ __half g_w2h[(long long)NLAYER * DIM * MLPD];
__device__ __half g_wqkv[(long long)NLAYER * NHEAD * 192 * DH]; // packed Q|K|V per head
__device__ float  g_bqkv[(long long)NLAYER * NHEAD * 192];

// ---------------- helpers ----------------
__device__ __forceinline__ uint32_t smem_u32(const void* p) {
    uint32_t a;
    asm("{ .reg .u64 t; cvta.to.shared.u64 t, %1; cvt.u32.u64 %0, t; }" : "=r"(a) : "l"(p));
    return a;
}

__device__ __forceinline__ void ldm4(uint32_t* r, uint32_t addr) {
    asm volatile("ldmatrix.sync.aligned.m8n8.x4.shared.b16 {%0,%1,%2,%3}, [%4];"
                 : "=r"(r[0]), "=r"(r[1]), "=r"(r[2]), "=r"(r[3]) : "r"(addr));
}

__device__ __forceinline__ void mma_fp16(float* c, const uint32_t* a, uint32_t b0, uint32_t b1) {
    asm volatile(
        "mma.sync.aligned.m16n8k16.row.col.f32.f16.f16.f32 "
        "{%0,%1,%2,%3}, {%4,%5,%6,%7}, {%8,%9}, {%0,%1,%2,%3};"
        : "+f"(c[0]), "+f"(c[1]), "+f"(c[2]), "+f"(c[3])
        : "r"(a[0]), "r"(a[1]), "r"(a[2]), "r"(a[3]), "r"(b0), "r"(b1));
}

__device__ __forceinline__ uint32_t pack_h2(float lo, float hi) {
    __half2 h = __floats2half2_rn(lo, hi);
    return *(uint32_t*)&h;
}

__device__ __forceinline__ void cp_async16(uint32_t dst, const void* src, int valid) {
    asm volatile("cp.async.cg.shared.global [%0], [%1], 16, %2;"
                 :: "r"(dst), "l"(src), "r"(valid));
}
__device__ __forceinline__ void cp_commit() { asm volatile("cp.async.commit_group;"); }
__device__ __forceinline__ void cp_wait1() { asm volatile("cp.async.wait_group 1;"); }
__device__ __forceinline__ void cp_wait0() { asm volatile("cp.async.wait_group 0;"); }

// ======================================================================
//  fp16 batched NT GEMM: 128x128 CTA tile, 8 warps (64x32 warp tile)
//  modes: 0 = fp32 out (+R), 1 = fp16 out, 2 = QKV routing (q/k/vT)
//  ksplit>1: blockIdx.z = K-split index, epilogue atomicAdd into Cf
// ======================================================================
#define RSB 80
#define PLB (128 * RSB)
#define STB (2 * PLB)
#define NSTAGE 3
#define SMEM_MMA (NSTAGE * STB)

__global__ __launch_bounds__(256, 2)
void gemm_fp16_kernel(const __half* __restrict__ Ah, long long lda, long long sA1, long long sA2,
                      const __half* __restrict__ Bh, long long ldb, long long sB1, long long sB2,
                      float* __restrict__ Cf, __half* __restrict__ Ch,
                      long long ldc, long long sC1, long long sC2,
                      const float* __restrict__ bias, long long sb1, long long sb2,
                      const float* __restrict__ R,
                      __half* __restrict__ Kout, __half* __restrict__ Vout,
                      int M, int N, int K, int gelu, int z2, int mode, int seq, int ksplit)
{
    extern __shared__ char sm[];
    uint32_t smb = smem_u32(sm);
    const int tid = threadIdx.x;
    const int lid = tid & 31;
    const int wid = tid >> 5;
    const int wm = wid >> 2;          // 0..1
    const int wn = wid & 3;           // 0..3
    const int m0 = blockIdx.y * 128;
    const int n0 = blockIdx.x * 128;
    int head = 0;
    int split = 0;
    int kbase = 0;
    int Kloc = K;

    if (ksplit > 1) {
        split = blockIdx.z;
        Kloc = K / ksplit;
        kbase = split * Kloc;
    } else {
        int bz = blockIdx.z;
        int i1 = bz / z2, i2 = bz % z2;
        head = i2;
        Ah += i1 * sA1 + i2 * sA2;
        Bh += i1 * sB1 + i2 * sB2;
        if (Cf) Cf += i1 * sC1 + i2 * sC2;
        if (Ch && mode != 2) Ch += i1 * sC1 + i2 * sC2;
        if (bias) bias += i1 * sb1 + i2 * sb2;
    }

    const int nch = Kloc >> 5;

    auto load_stage = [&](int s, int chunk) {
        int k0 = kbase + (chunk << 5);
        uint32_t sbase = smb + s * STB;
        #pragma unroll
        for (int t = 0; t < 4; t++) {
            int id = tid + t * 256;
            int plane = id >> 9;
            int rc = id & 511;
            int row = rc >> 2;
            int c = rc & 3;
            uint32_t dst = sbase + plane * PLB + row * RSB + c * 16;
            const __half* src;
            int valid;
            if (plane == 0) {
                int gm = m0 + row;
                int gmc = gm < M ? gm : M - 1;
                src = Ah + (long long)gmc * lda + k0 + c * 8;
                valid = (gm < M) ? 16 : 0;
            } else {
                int gn = n0 + row;
                int gnc = gn < N ? gn : N - 1;
                src = Bh + (long long)gnc * ldb + k0 + c * 8;
                valid = (gn < N) ? 16 : 0;
            }
            cp_async16(dst, src, valid);
        }
        cp_commit();
    };

    float acc[4][4][4];
    #pragma unroll
    for (int i = 0; i < 4; i++)
        #pragma unroll
        for (int j = 0; j < 4; j++)
            #pragma unroll
            for (int r = 0; r < 4; r++) acc[i][j][r] = 0.f;

    load_stage(0, 0);
    if (nch > 1) load_stage(1, 1);

    for (int i = 0; i < nch; i++) {
        if (i == nch - 1) cp_wait0(); else cp_wait1();
        __syncthreads();
        if (i + 2 < nch) load_stage((i + 2) % NSTAGE, i + 2);

        uint32_t sA = smb + (i % NSTAGE) * STB;
        uint32_t sB = sA + PLB;
        #pragma unroll
        for (int kk = 0; kk < 2; kk++) {
            int kt = kk << 4;
            uint32_t af[4][4];
            #pragma unroll
            for (int t = 0; t < 4; t++) {
                int m = wm * 64 + t * 16;
                uint32_t row = m + ((lid >> 3) & 1) * 8 + (lid & 7);
                uint32_t koff = kt + (lid >> 4) * 8;
                ldm4(af[t], sA + row * RSB + koff * 2);
            }
            uint32_t bf[2][4];
            #pragma unroll
            for (int p = 0; p < 2; p++) {
                int n = wn * 32 + p * 16;
                uint32_t row = n + (lid >> 4) * 8 + (lid & 7);
                uint32_t koff = kt + ((lid >> 3) & 1) * 8;
                ldm4(bf[p], sB + row * RSB + koff * 2);
            }
            #pragma unroll
            for (int t = 0; t < 4; t++) {
                #pragma unroll
                for (int j = 0; j < 4; j++) {
                    uint32_t b0 = bf[j >> 1][(j & 1) * 2], b1 = bf[j >> 1][(j & 1) * 2 + 1];
                    mma_fp16(acc[t][j], af[t], b0, b1);
                }
            }
        }
        __syncthreads();
    }

    // ---- epilogue ----
    #pragma unroll
    for (int t = 0; t < 4; t++) {
        #pragma unroll
        for (int j = 0; j < 4; j++) {
            int col = n0 + wn * 32 + j * 8 + (lid & 3) * 2;
            #pragma unroll
            for (int h = 0; h < 2; h++) {
                int row = m0 + wm * 64 + t * 16 + (lid >> 2) + h * 8;
                if (row >= M) continue;
                #pragma unroll
                for (int e = 0; e < 2; e++) {
                    int c = col + e;
                    if (c >= N) continue;
                    float v = acc[t][j][h * 2 + e];
                    if (bias && split == 0) v += bias[c];
                    if (gelu) v = 0.5f * v * (1.0f + erff(v * 0.70710678118654752f));
                    if (mode == 0) {
                        long long base = (long long)row * ldc + c;
                        if (ksplit > 1) {
                            atomicAdd(&Cf[base], v);
                        } else {
                            float r = R ? R[base] : 0.f;
                            Cf[base] = v + r;
                        }
                    } else if (mode == 1) {
                        Ch[(long long)row * ldc + c] = __float2half_rn(v);
                    } else {
                        // QKV routing: c<64 -> q, c<128 -> k, else -> vT (SEQ compile-time)
                        __half hv = __float2half_rn(v);
                        if (c < 64) {
                            Ch[(long long)row * DIM + head * DH + c] = hv;
                        } else if (c < 128) {
                            Kout[(long long)row * DIM + head * DH + (c - 64)] = hv;
                        } else {
                            int nb = row / SEQ, s = row - nb * SEQ;
                            Vout[((long long)(nb * NHEAD + head) * DH + (c - 128)) * ALD + s] = hv;
                        }
                    }
                }
            }
        }
    }
}

// ======================================================================
//  fused flash attention: per (qtile, h, n) CTA
// ======================================================================
#define FA_RSQ 144
#define FA_RSV 464
#define FA_SM_Q 0
#define FA_SM_K (128 * FA_RSQ)
#define FA_SM_V (FA_SM_K + ALD * FA_RSQ)
#define FA_SMEM (FA_SM_V + DH * FA_RSV)

__global__ __launch_bounds__(256, 1)
void flash_kernel(const __half* __restrict__ qh, const __half* __restrict__ kh,
                  const __half* __restrict__ vth, float* __restrict__ outb)
{
    extern __shared__ char sm[];
    uint32_t smb = smem_u32(sm);
    const int tid = threadIdx.x;
    const int lid = tid & 31;
    const int wid = tid >> 5;
    const int q0 = blockIdx.x * 128;
    const int h  = blockIdx.y;
    const int n  = blockIdx.z;
    const int wr = wid * 16;

    const long long qbase = ((long long)n * SEQ) * DIM + h * DH;
    const long long vbase = ((long long)n * NHEAD + h) * (long long)DH * ALD;

    #pragma unroll
    for (int t = 0; t < 4; t++) {
        int id = tid + t * 256;
        int row = id >> 3, ch = id & 7;
        int s = q0 + row; if (s >= SEQ) s = SEQ - 1;
        *(uint4*)(sm + FA_SM_Q + row * FA_RSQ + ch * 16) =
            *(const uint4*)(qh + qbase + (long long)s * DIM + ch * 8);
    }
    #pragma unroll
    for (int t = 0; t < 7; t++) {
        int id = tid + t * 256;
        int row = id >> 3, ch = id & 7;
        int s = row; if (s >= SEQ) s = SEQ - 1;
        *(uint4*)(sm + FA_SM_K + row * FA_RSQ + ch * 16) =
            *(const uint4*)(kh + qbase + (long long)s * DIM + ch * 8);
    }
    for (int id = tid; id < DH * 28; id += 256) {
        int row = id / 28, ch = id % 28;
        *(uint4*)(sm + FA_SM_V + row * FA_RSV + ch * 16) =
            *(const uint4*)(vth + vbase + (long long)row * ALD + ch * 8);
    }
    __syncthreads();

    uint32_t aq[4][4];
    #pragma unroll
    for (int kt = 0; kt < 4; kt++) {
        uint32_t row = wr + ((lid >> 3) & 1) * 8 + (lid & 7);
        uint32_t koff = kt * 16 + (lid >> 4) * 8;
        ldm4(aq[kt], smb + FA_SM_Q + row * FA_RSQ + koff * 2);
    }
    float acc[28][4];
    #pragma unroll
    for (int j = 0; j < 28; j++)
        #pragma unroll
        for (int r = 0; r < 4; r++) acc[j][r] = 0.f;

    #pragma unroll
    for (int nt = 0; nt < 14; nt++) {
        #pragma unroll
        for (int kt = 0; kt < 4; kt++) {
            uint32_t bk[4];
            uint32_t row = nt * 16 + (lid >> 4) * 8 + (lid & 7);
            uint32_t koff = kt * 16 + ((lid >> 3) & 1) * 8;
            ldm4(bk, smb + FA_SM_K + row * FA_RSQ + koff * 2);
            mma_fp16(acc[nt * 2],     aq[kt], bk[0], bk[1]);
            mma_fp16(acc[nt * 2 + 1], aq[kt], bk[2], bk[3]);
        }
    }

    float m0 = -1e30f, m1 = -1e30f;
    #pragma unroll
    for (int j = 0; j < 28; j++) {
        int c0 = j * 8 + (lid & 3) * 2;
        if (c0 >= SEQ)     { acc[j][0] = -1e30f; acc[j][2] = -1e30f; }
        if (c0 + 1 >= SEQ) { acc[j][1] = -1e30f; acc[j][3] = -1e30f; }
        m0 = fmaxf(m0, fmaxf(acc[j][0], acc[j][1]));
        m1 = fmaxf(m1, fmaxf(acc[j][2], acc[j][3]));
    }
    m0 = fmaxf(m0, __shfl_xor_sync(0xffffffffu, m0, 1));
    m0 = fmaxf(m0, __shfl_xor_sync(0xffffffffu, m0, 2));
    m1 = fmaxf(m1, __shfl_xor_sync(0xffffffffu, m1, 1));
    m1 = fmaxf(m1, __shfl_xor_sync(0xffffffffu, m1, 2));

    float s0 = 0.f, s1 = 0.f;
    #pragma unroll
    for (int j = 0; j < 28; j++) {
        acc[j][0] = __expf((acc[j][0] - m0) * 0.125f);
        acc[j][1] = __expf((acc[j][1] - m0) * 0.125f);
        acc[j][2] = __expf((acc[j][2] - m1) * 0.125f);
        acc[j][3] = __expf((acc[j][3] - m1) * 0.125f);
        s0 += acc[j][0] + acc[j][1];
        s1 += acc[j][2] + acc[j][3];
    }
    s0 += __shfl_xor_sync(0xffffffffu, s0, 1);
    s0 += __shfl_xor_sync(0xffffffffu, s0, 2);
    s1 += __shfl_xor_sync(0xffffffffu, s1, 1);
    s1 += __shfl_xor_sync(0xffffffffu, s1, 2);
    float inv0 = 1.0f / s0, inv1 = 1.0f / s1;

    float o[8][4];
    #pragma unroll
    for (int g = 0; g < 8; g++)
        #pragma unroll
        for (int r = 0; r < 4; r++) o[g][r] = 0.f;

    #pragma unroll
    for (int kt2 = 0; kt2 < 14; kt2++) {
        int j0 = kt2 * 2, j1 = j0 + 1;
        uint32_t af[4];
        af[0] = pack_h2(acc[j0][0], acc[j0][1]);
        af[1] = pack_h2(acc[j0][2], acc[j0][3]);
        af[2] = pack_h2(acc[j1][0], acc[j1][1]);
        af[3] = pack_h2(acc[j1][2], acc[j1][3]);
        #pragma unroll
        for (int g = 0; g < 4; g++) {
            uint32_t bv[4];
            uint32_t row = g * 16 + (lid >> 4) * 8 + (lid & 7);
            uint32_t koff = kt2 * 16 + ((lid >> 3) & 1) * 8;
            ldm4(bv, smb + FA_SM_V + row * FA_RSV + koff * 2);
            mma_fp16(o[g * 2],     af, bv[0], bv[1]);
            mma_fp16(o[g * 2 + 1], af, bv[2], bv[3]);
        }
    }

    int r0 = q0 + wr + (lid >> 2);
    int r1 = r0 + 8;
    #pragma unroll
    for (int g = 0; g < 8; g++) {
        int c = h * DH + g * 8 + (lid & 3) * 2;
        if (r0 < SEQ) {
            long long b = ((long long)n * SEQ + r0) * DIM + c;
            outb[b]     += o[g][0] * inv0;
            outb[b + 1] += o[g][1] * inv0;
        }
        if (r1 < SEQ) {
            long long b = ((long long)n * SEQ + r1) * DIM + c;
            outb[b]     += o[g][2] * inv1;
            outb[b + 1] += o[g][3] * inv1;
        }
    }
}

// ======================================================================
//  small kernels
// ======================================================================
__global__ void zero_fp16_kernel(__half* __restrict__ p, long long n) {
    long long i = ((long long)blockIdx.x * 256 + threadIdx.x) * 8;
    if (i >= n) return;
    *(uint4*)(p + i) = make_uint4(0, 0, 0, 0);
}

// fp32 -> fp16, 8 elements per thread
__global__ void cvt_kernel(const float* __restrict__ x, __half* __restrict__ h, long long n) {
    long long i = ((long long)blockIdx.x * 256 + threadIdx.x) * 8;
    if (i >= n) return;
    float4 a = *(const float4*)(x + i);
    float4 b = *(const float4*)(x + i + 4);
    uint4 o;
    o.x = pack_h2(a.x, a.y);
    o.y = pack_h2(a.z, a.w);
    o.z = pack_h2(b.x, b.y);
    o.w = pack_h2(b.z, b.w);
    *(uint4*)(h + i) = o;
}

// pack Wq/Wk/Wv [L][H][64][64] fp32 -> wqkv [L][H][192][64] fp16
__global__ void pack_qkv_w_kernel(const float* __restrict__ Wq, const float* __restrict__ Wk,
                                  const float* __restrict__ Wv, __half* __restrict__ out) {
    long long idx = (long long)blockIdx.x * 256 + threadIdx.x;
    const long long total = (long long)NLAYER * NHEAD * 192 * DH;
    if (idx >= total) return;
    int c = (int)(idx & 63);
    long long t = idx >> 6;
    int r = (int)(t % 192);
    long long lh = t / 192;
    const float* src = (r < 64) ? Wq : (r < 128 ? Wk : Wv);
    int rr = r & 63;
    out[idx] = __float2half_rn(src[(lh * 64 + rr) * 64 + c]);
}

// pack bq/bk/bv [L][H][64] fp32 -> bqkv [L][H][192] fp32
__global__ void pack_qkv_b_kernel(const float* __restrict__ bq, const float* __restrict__ bk,
                                  const float* __restrict__ bv, float* __restrict__ out) {
    long long idx = (long long)blockIdx.x * 256 + threadIdx.x;
    const long long total = (long long)NLAYER * NHEAD * 192;
    if (idx >= total) return;
    int r = (int)(idx % 192);
    long long lh = idx / 192;
    const float* src = (r < 64) ? bq : (r < 128 ? bk : bv);
    out[idx] = src[lh * 64 + (r & 63)];
}

__global__ void patchify_kernel(const float* __restrict__ x, __half* __restrict__ ph) {
    long long idx = (long long)blockIdx.x * 256 + threadIdx.x;
    const long long total = (long long)BATCH * NPATCH * DIM;
    if (idx >= total) return;
    int e = (int)(idx % DIM);
    long long r = idx / DIM;
    int p = (int)(r % NPATCH);
    int n = (int)(r / NPATCH);
    int c = e / 256;
    int hw = e % 256;
    int hi = hw / 16, wi = hw % 16;
    int pi = p / 14, pj = p % 14;
    ph[idx] = __float2half_rn(
        x[(((long long)n * 3 + c) * 224 + (pi * 16 + hi)) * 224 + (pj * 16 + wi)]);
}

__global__ void assemble_kernel(const float* __restrict__ tmp, const float* __restrict__ cls,
                                float* __restrict__ out) {
    long long idx = (long long)blockIdx.x * 256 + threadIdx.x;
    const long long total = (long long)BATCH * SEQ * DIM;
    if (idx >= total) return;
    int d = (int)(idx % DIM);
    long long r = idx / DIM;
    int s = (int)(r % SEQ);
    int n = (int)(r / SEQ);
    float v = (s == 0) ? cls[d] : tmp[((long long)n * NPATCH + (s - 1)) * DIM + d];
    float pe;
    if ((s & 1) == 0) pe = sinf((float)s / powf(10000.0f, (float)d / (float)DIM));
    else              pe = cosf((float)s / powf(10000.0f, (float)(d - 1) / (float)DIM));
    out[idx] = v + pe;
}

// warp-per-row layernorm: 8 rows per 256-thread block, shuffle-only reduction
__global__ __launch_bounds__(256)
void layernorm_kernel(const float* __restrict__ x, const float* __restrict__ g,
                      const float* __restrict__ b, __half* __restrict__ yh) {
    int warp = threadIdx.x >> 5;
    int lid = threadIdx.x & 31;
    long long row = (long long)blockIdx.x * 8 + warp;
    const float4* p = (const float4*)(x + row * DIM);
    const float4* gv = (const float4*)g;
    const float4* bv = (const float4*)b;

    float4 v[6];
    float s = 0.f, s2 = 0.f;
    #pragma unroll
    for (int k = 0; k < 6; k++) {
        v[k] = p[lid + k * 32];
        s  += v[k].x + v[k].y + v[k].z + v[k].w;
        s2 += v[k].x * v[k].x + v[k].y * v[k].y + v[k].z * v[k].z + v[k].w * v[k].w;
    }
    #pragma unroll
    for (int o = 16; o > 0; o >>= 1) {
        s  += __shfl_xor_sync(0xffffffffu, s, o);
        s2 += __shfl_xor_sync(0xffffffffu, s2, o);
    }
    float mu = s * (1.0f / DIM);
    float var = s2 * (1.0f / DIM) - mu * mu;
    float inv = rsqrtf(var + 1e-5f);

    uint2* out = (uint2*)(yh + row * DIM);
    #pragma unroll
    for (int k = 0; k < 6; k++) {
        float4 gg = gv[lid + k * 32];
        float4 bb = bv[lid + k * 32];
        float r0 = (v[k].x - mu) * inv * gg.x + bb.x;
        float r1 = (v[k].y - mu) * inv * gg.y + bb.y;
        float r2 = (v[k].z - mu) * inv * gg.z + bb.z;
        float r3 = (v[k].w - mu) * inv * gg.w + bb.w;
        uint2 o;
        o.x = pack_h2(r0, r1);
        o.y = pack_h2(r2, r3);
        out[lid + k * 32] = o;
    }
}

// ======================================================================
//  generic SIMT GEMM (head only)
// ======================================================================
#define BM 64
#define BN 64
#define BK 16

__global__ void gemm_simt_kernel(
    const float* __restrict__ A, int lda,
    const float* __restrict__ B, int ldb,
    float* __restrict__ C, int ldc,
    const float* __restrict__ bias,
    int M, int N, int K)
{
    __shared__ float As[BK][BM];
    __shared__ float Bs[BK][BN];
    int bm = blockIdx.y * BM;
    int bn = blockIdx.x * BN;
    int tid = threadIdx.x;
    int tx = tid % 16, ty = tid / 16;
    float acc[4][4] = {};
    for (int k0 = 0; k0 < K; k0 += BK) {
        #pragma unroll
        for (int i = 0; i < 4; i++) {
            int idx = tid + i * 256;
            int m = idx / BK, kk = idx % BK;
            int gm = bm + m, gk = k0 + kk;
            As[kk][m] = (gm < M && gk < K) ? A[(long long)gm * lda + gk] : 0.f;
        }
        #pragma unroll
        for (int i = 0; i < 4; i++) {
            int idx = tid + i * 256;
            int n = idx / BK, kk = idx % BK;
            int gn = bn + n, gk = k0 + kk;
            Bs[kk][n] = (gn < N && gk < K) ? B[(long long)gn * ldb + gk] : 0.f;
        }
        __syncthreads();
        #pragma unroll
        for (int kk = 0; kk < BK; kk++) {
            float a[4], b[4];
            #pragma unroll
            for (int i = 0; i < 4; i++) a[i] = As[kk][ty * 4 + i];
            #pragma unroll
            for (int j = 0; j < 4; j++) b[j] = Bs[kk][tx * 4 + j];
            #pragma unroll
            for (int i = 0; i < 4; i++)
                #pragma unroll
                for (int j = 0; j < 4; j++)
                    acc[i][j] += a[i] * b[j];
        }
        __syncthreads();
    }
    #pragma unroll
    for (int i = 0; i < 4; i++) {
        int gm = bm + ty * 4 + i;
        if (gm >= M) continue;
        #pragma unroll
        for (int j = 0; j < 4; j++) {
            int gn = bn + tx * 4 + j;
            if (gn >= N) continue;
            C[(long long)gm * ldc + gn] = acc[i][j] + (bias ? bias[gn] : 0.f);
        }
    }
}

// ======================================================================
//  launch helper
// ======================================================================
struct MArgs {
    const __half *Ah; long long lda, sA1, sA2;
    const __half *Bh; long long ldb, sB1, sB2;
    float* Cf; __half* Ch; long long ldc, sC1, sC2;
    const float* bias; long long sb1, sb2;
    const float* R;
    __half *Kout, *Vout;
    int M, N, K; int gelu; int z2; int Z; int mode; int ksplit;
};

static void launch_mma(const MArgs& a, cudaStream_t stream) {
    static bool attr_set = false;
    if (!attr_set) {
        cudaFuncSetAttribute(gemm_fp16_kernel,
                             cudaFuncAttributeMaxDynamicSharedMemorySize, SMEM_MMA);
        cudaFuncSetAttribute(flash_kernel,
                             cudaFuncAttributeMaxDynamicSharedMemorySize, FA_SMEM);
        attr_set = true;
    }
    int zdim = (a.ksplit > 1) ? a.ksplit : a.Z;
    dim3 grid((a.N + 127) / 128, (a.M + 127) / 128, zdim);
    gemm_fp16_kernel<<<grid, 256, SMEM_MMA, stream>>>(
        a.Ah, a.lda, a.sA1, a.sA2,
        a.Bh, a.ldb, a.sB1, a.sB2,
        a.Cf, a.Ch, a.ldc, a.sC1, a.sC2,
        a.bias, a.sb1, a.sb2, a.R, a.Kout, a.Vout,
        a.M, a.N, a.K, a.gelu, a.z2, a.mode, SEQ, a.ksplit);
}

// ======================================================================
//  orchestration (single stream)
// ======================================================================
extern "C" void kernel_launch(void* const* d_in, const int* in_sizes, int n_in,
                              void* d_out, int out_size) {
    (void)in_sizes; (void)n_in; (void)out_size;
    const float* x    = (const float*)d_in[0];
    const float* Wp   = (const float*)d_in[1];
    const float* bp   = (const float*)d_in[2];
    const float* cls  = (const float*)d_in[3];
    const float* ln1g = (const float*)d_in[4];
    const float* ln1b = (const float*)d_in[5];
    const float* Wq   = (const float*)d_in[6];
    const float* bq   = (const float*)d_in[7];
    const float* Wk   = (const float*)d_in[8];
    const float* bk   = (const float*)d_in[9];
    const float* Wv   = (const float*)d_in[10];
    const float* bv   = (const float*)d_in[11];
    const float* ln2g = (const float*)d_in[12];
    const float* ln2b = (const float*)d_in[13];
    const float* W1   = (const float*)d_in[14];
    const float* b1   = (const float*)d_in[15];
    const float* W2   = (const float*)d_in[16];
    const float* b2   = (const float*)d_in[17];
    const float* Wh   = (const float*)d_in[18];
    const float* bh   = (const float*)d_in[19];
    float* out_final  = (float*)d_out;

    float *outb, *ptmp, *bqkv;
    __half *ph, *xh, *mh, *qh, *kh, *vth;
    __half *wph, *w1h, *w2h, *wqkv;
    cudaGetSymbolAddress((void**)&outb, g_out);
    cudaGetSymbolAddress((void**)&ptmp, g_ptmp);
    cudaGetSymbolAddress((void**)&ph,   g_ph);
    cudaGetSymbolAddress((void**)&xh,   g_xh);
    cudaGetSymbolAddress((void**)&mh,   g_mh);
    cudaGetSymbolAddress((void**)&qh,   g_qh);
    cudaGetSymbolAddress((void**)&kh,   g_kh);
    cudaGetSymbolAddress((void**)&vth,  g_vth);
    cudaGetSymbolAddress((void**)&wph,  g_wph);
    cudaGetSymbolAddress((void**)&w1h,  g_w1h);
    cudaGetSymbolAddress((void**)&w2h,  g_w2h);
    cudaGetSymbolAddress((void**)&wqkv, g_wqkv);
    cudaGetSymbolAddress((void**)&bqkv, g_bqkv);

    cudaStream_t stream = 0;
    const int ROWS = BATCH * SEQ;                    // 12608

    // 0) weight converts + QKV pack + vT pad zero
    {
        long long n;
        n = (long long)DIM * DIM;
        cvt_kernel<<<(unsigned)((n / 8 + 255) / 256), 256, 0, stream>>>(Wp, wph, n);
        n = (long long)NLAYER * MLPD * DIM;
        cvt_kernel<<<(unsigned)((n / 8 + 255) / 256), 256, 0, stream>>>(W1, w1h, n);
        cvt_kernel<<<(unsigned)((n / 8 + 255) / 256), 256, 0, stream>>>(W2, w2h, n);
        n = (long long)NLAYER * NHEAD * 192 * DH;
        pack_qkv_w_kernel<<<(unsigned)((n + 255) / 256), 256, 0, stream>>>(Wq, Wk, Wv, wqkv);
        n = (long long)NLAYER * NHEAD * 192;
        pack_qkv_b_kernel<<<(unsigned)((n + 255) / 256), 256, 0, stream>>>(bq, bk, bv, bqkv);
        n = (long long)BATCH * NHEAD * DH * ALD;
        zero_fp16_kernel<<<(unsigned)((n / 8 + 255) / 256), 256, 0, stream>>>(vth, n);
    }

    // 1) patchify -> fp16
    {
        long long total = (long long)BATCH * NPATCH * DIM;
        patchify_kernel<<<(unsigned)((total + 255) / 256), 256, 0, stream>>>(x, ph);
    }
    // 2) patch embedding: ptmp = patches @ Wp^T + bp
    {
        MArgs a = {};
        a.Ah = ph; a.lda = DIM;
        a.Bh = wph; a.ldb = DIM;
        a.Cf = ptmp; a.ldc = DIM;
        a.bias = bp;
        a.M = BATCH * NPATCH; a.N = DIM; a.K = DIM;
        a.z2 = 1; a.Z = 1; a.mode = 0; a.ksplit = 1;
        launch_mma(a, stream);
    }
    // 3) assemble tokens + cls + positional embedding
    {
        long long total = (long long)BATCH * SEQ * DIM;
        assemble_kernel<<<(unsigned)((total + 255) / 256), 256, 0, stream>>>(ptmp, cls, outb);
    }

    for (int l = 0; l < NLAYER; l++) {
        // --- ln1 -> fp16 ---
        layernorm_kernel<<<ROWS / 8, 256, 0, stream>>>(outb, ln1g + l * DIM, ln1b + l * DIM, xh);

        // --- fused QKV projection (one launch, Z=12 heads, N=192) ---
        {
            MArgs a = {};
            a.Ah = xh; a.lda = DIM; a.sA2 = DH;
            a.Bh = wqkv + (long long)l * NHEAD * 192 * DH; a.ldb = DH; a.sB2 = 192 * DH;
            a.Ch = qh; a.Kout = kh; a.Vout = vth;
            a.bias = bqkv + (long long)l * NHEAD * 192; a.sb2 = 192;
            a.M = ROWS; a.N = 192; a.K = DH;
            a.z2 = NHEAD; a.Z = NHEAD; a.mode = 2; a.ksplit = 1;
            launch_mma(a, stream);
        }

        // --- fused attention + residual ---
        {
            dim3 grid(2, NHEAD, BATCH);
            flash_kernel<<<grid, 256, FA_SMEM, stream>>>(qh, kh, vth, outb);
        }

        // --- ln2 -> fp16 ---
        layernorm_kernel<<<ROWS / 8, 256, 0, stream>>>(outb, ln2g + l * DIM, ln2b + l * DIM, xh);

        // --- MLP1 + GELU -> fp16 ---
        {
            MArgs a = {};
            a.Ah = xh; a.lda = DIM;
            a.Bh = w1h + (long long)l * MLPD * DIM; a.ldb = DIM;
            a.Ch = mh; a.ldc = MLPD;
            a.bias = b1 + (long long)l * MLPD;
            a.M = ROWS; a.N = MLPD; a.K = DIM; a.gelu = 1;
            a.z2 = 1; a.Z = 1; a.mode = 1; a.ksplit = 1;
            launch_mma(a, stream);
        }
        // --- MLP2 + residual -> fp32, split-K=2 (atomicAdd onto outb) ---
        {
            MArgs a = {};
            a.Ah = mh; a.lda = MLPD;
            a.Bh = w2h + (long long)l * DIM * MLPD; a.ldb = MLPD;
            a.Cf = outb; a.ldc = DIM;
            a.bias = b2 + (long long)l * DIM;
            a.M = ROWS; a.N = DIM; a.K = MLPD;
            a.z2 = 1; a.Z = 1; a.mode = 0; a.ksplit = 2;
            launch_mma(a, stream);
        }
    }

    // --- head: out_final = out[:,0,:] @ Wh^T + bh (SIMT, tiny) ---
    {
        dim3 grid((OUTD + BN - 1) / BN, (BATCH + BM - 1) / BM, 1);
        gemm_simt_kernel<<<grid, 256, 0, stream>>>(
            outb, (int)((long long)SEQ * DIM), Wh, DIM, out_final, OUTD, bh, BATCH, OUTD, DIM);
    }
}

// round 17
// speedup vs baseline: 1.0304x; 1.0015x over previous
#include <cuda_runtime.h>
#include <cuda_fp16.h>
#include <cstdint>

// ---------------- problem constants ----------------
#define BATCH 64
#define SEQ 197
#define NPATCH 196
#define DIM 768
#define NHEAD 12
#define DH 64
#define MLPD 3072
#define OUTD 1000
#define NLAYER 12
#define ALD 224                 // padded attention K length (mult of 32)

// ---------------- scratch (static device globals; no allocation) ----------------
__device__ float g_out[(long long)BATCH * SEQ * DIM];          // residual stream
__device__ float g_ptmp[(long long)BATCH * NPATCH * DIM];      // patch-embed fp32 out

// fp16 activation / weight buffers
__device__ __half g_ph[(long long)BATCH * NPATCH * DIM];   // patches
__device__ __half g_xh[(long long)BATCH * SEQ * DIM];      // ln out
__device__ __half g_mh[(long long)BATCH * SEQ * MLPD];     // mlp hidden
__device__ __half g_qh[(long long)BATCH * SEQ * DIM];
__device__ __half g_kh[(long long)BATCH * SEQ * DIM];
__device__ __half g_vth[(long long)BATCH * NHEAD * DH * ALD];  // V^T [n][h][o][s-pad]
__device__ __half g_wph[(long long)DIM * DIM];
__device__ __half g_w1h[(long long)NLAYER * MLPD * DIM];
__device__ __half g_w2h[(long long)NLAYER * DIM * MLPD];
__device__ __half g_wqkv[(long long)NLAYER * NHEAD * 192 * DH]; // packed Q|K|V per head
__device__ float  g_bqkv[(long long)NLAYER * NHEAD * 192];

// ---------------- helpers ----------------
__device__ __forceinline__ uint32_t smem_u32(const void* p) {
    uint32_t a;
    asm("{ .reg .u64 t; cvta.to.shared.u64 t, %1; cvt.u32.u64 %0, t; }" : "=r"(a) : "l"(p));
    return a;
}

__device__ __forceinline__ void ldm4(uint32_t* r, uint32_t addr) {
    asm volatile("ldmatrix.sync.aligned.m8n8.x4.shared.b16 {%0,%1,%2,%3}, [%4];"
                 : "=r"(r[0]), "=r"(r[1]), "=r"(r[2]), "=r"(r[3]) : "r"(addr));
}

__device__ __forceinline__ void mma_fp16(float* c, const uint32_t* a, uint32_t b0, uint32_t b1) {
    asm volatile(
        "mma.sync.aligned.m16n8k16.row.col.f32.f16.f16.f32 "
        "{%0,%1,%2,%3}, {%4,%5,%6,%7}, {%8,%9}, {%0,%1,%2,%3};"
        : "+f"(c[0]), "+f"(c[1]), "+f"(c[2]), "+f"(c[3])
        : "r"(a[0]), "r"(a[1]), "r"(a[2]), "r"(a[3]), "r"(b0), "r"(b1));
}

__device__ __forceinline__ uint32_t pack_h2(float lo, float hi) {
    __half2 h = __floats2half2_rn(lo, hi);
    return *(uint32_t*)&h;
}

__device__ __forceinline__ void cp_async16(uint32_t dst, const void* src, int valid) {
    asm volatile("cp.async.cg.shared.global [%0], [%1], 16, %2;"
                 :: "r"(dst), "l"(src), "r"(valid));
}
__device__ __forceinline__ void cp_commit() { asm volatile("cp.async.commit_group;"); }
__device__ __forceinline__ void cp_wait1() { asm volatile("cp.async.wait_group 1;"); }
__device__ __forceinline__ void cp_wait0() { asm volatile("cp.async.wait_group 0;"); }

// ======================================================================
//  fp16 batched NT GEMM: 128x128 CTA tile, 8 warps (64x32 warp tile)
//  modes: 0 = fp32 out (+R), 1 = fp16 out, 2 = QKV routing (q/k/vT)
//  ksplit>1: blockIdx.z = K-split index, epilogue atomicAdd into Cf
// ======================================================================
#define RSB 80
#define PLB (128 * RSB)
#define STB (2 * PLB)
#define NSTAGE 3
#define SMEM_MMA (NSTAGE * STB)

__global__ __launch_bounds__(256, 2)
void gemm_fp16_kernel(const __half* __restrict__ Ah, long long lda, long long sA1, long long sA2,
                      const __half* __restrict__ Bh, long long ldb, long long sB1, long long sB2,
                      float* __restrict__ Cf, __half* __restrict__ Ch,
                      long long ldc, long long sC1, long long sC2,
                      const float* __restrict__ bias, long long sb1, long long sb2,
                      const float* __restrict__ R,
                      __half* __restrict__ Kout, __half* __restrict__ Vout,
                      int M, int N, int K, int gelu, int z2, int mode, int seq, int ksplit)
{
    extern __shared__ char sm[];
    uint32_t smb = smem_u32(sm);
    const int tid = threadIdx.x;
    const int lid = tid & 31;
    const int wid = tid >> 5;
    const int wm = wid >> 2;          // 0..1
    const int wn = wid & 3;           // 0..3
    const int m0 = blockIdx.y * 128;
    const int n0 = blockIdx.x * 128;
    int head = 0;
    int split = 0;
    int kbase = 0;
    int Kloc = K;

    if (ksplit > 1) {
        split = blockIdx.z;
        Kloc = K / ksplit;
        kbase = split * Kloc;
    } else {
        int bz = blockIdx.z;
        int i1 = bz / z2, i2 = bz % z2;
        head = i2;
        Ah += i1 * sA1 + i2 * sA2;
        Bh += i1 * sB1 + i2 * sB2;
        if (Cf) Cf += i1 * sC1 + i2 * sC2;
        if (Ch && mode != 2) Ch += i1 * sC1 + i2 * sC2;
        if (bias) bias += i1 * sb1 + i2 * sb2;
    }

    const int nch = Kloc >> 5;

    auto load_stage = [&](int s, int chunk) {
        int k0 = kbase + (chunk << 5);
        uint32_t sbase = smb + s * STB;
        #pragma unroll
        for (int t = 0; t < 4; t++) {
            int id = tid + t * 256;
            int plane = id >> 9;
            int rc = id & 511;
            int row = rc >> 2;
            int c = rc & 3;
            uint32_t dst = sbase + plane * PLB + row * RSB + c * 16;
            const __half* src;
            int valid;
            if (plane == 0) {
                int gm = m0 + row;
                int gmc = gm < M ? gm : M - 1;
                src = Ah + (long long)gmc * lda + k0 + c * 8;
                valid = (gm < M) ? 16 : 0;
            } else {
                int gn = n0 + row;
                int gnc = gn < N ? gn : N - 1;
                src = Bh + (long long)gnc * ldb + k0 + c * 8;
                valid = (gn < N) ? 16 : 0;
            }
            cp_async16(dst, src, valid);
        }
        cp_commit();
    };

    float acc[4][4][4];
    #pragma unroll
    for (int i = 0; i < 4; i++)
        #pragma unroll
        for (int j = 0; j < 4; j++)
            #pragma unroll
            for (int r = 0; r < 4; r++) acc[i][j][r] = 0.f;

    load_stage(0, 0);
    if (nch > 1) load_stage(1, 1);

    for (int i = 0; i < nch; i++) {
        if (i == nch - 1) cp_wait0(); else cp_wait1();
        __syncthreads();
        if (i + 2 < nch) load_stage((i + 2) % NSTAGE, i + 2);

        uint32_t sA = smb + (i % NSTAGE) * STB;
        uint32_t sB = sA + PLB;
        #pragma unroll
        for (int kk = 0; kk < 2; kk++) {
            int kt = kk << 4;
            uint32_t af[4][4];
            #pragma unroll
            for (int t = 0; t < 4; t++) {
                int m = wm * 64 + t * 16;
                uint32_t row = m + ((lid >> 3) & 1) * 8 + (lid & 7);
                uint32_t koff = kt + (lid >> 4) * 8;
                ldm4(af[t], sA + row * RSB + koff * 2);
            }
            uint32_t bf[2][4];
            #pragma unroll
            for (int p = 0; p < 2; p++) {
                int n = wn * 32 + p * 16;
                uint32_t row = n + (lid >> 4) * 8 + (lid & 7);
                uint32_t koff = kt + ((lid >> 3) & 1) * 8;
                ldm4(bf[p], sB + row * RSB + koff * 2);
            }
            #pragma unroll
            for (int t = 0; t < 4; t++) {
                #pragma unroll
                for (int j = 0; j < 4; j++) {
                    uint32_t b0 = bf[j >> 1][(j & 1) * 2], b1 = bf[j >> 1][(j & 1) * 2 + 1];
                    mma_fp16(acc[t][j], af[t], b0, b1);
                }
            }
        }
        __syncthreads();
    }

    // ---- epilogue ----
    #pragma unroll
    for (int t = 0; t < 4; t++) {
        #pragma unroll
        for (int j = 0; j < 4; j++) {
            int col = n0 + wn * 32 + j * 8 + (lid & 3) * 2;
            #pragma unroll
            for (int h = 0; h < 2; h++) {
                int row = m0 + wm * 64 + t * 16 + (lid >> 2) + h * 8;
                if (row >= M) continue;
                #pragma unroll
                for (int e = 0; e < 2; e++) {
                    int c = col + e;
                    if (c >= N) continue;
                    float v = acc[t][j][h * 2 + e];
                    if (bias && split == 0) v += bias[c];
                    if (gelu) v = 0.5f * v * (1.0f + erff(v * 0.70710678118654752f));
                    if (mode == 0) {
                        long long base = (long long)row * ldc + c;
                        if (ksplit > 1) {
                            atomicAdd(&Cf[base], v);
                        } else {
                            float r = R ? R[base] : 0.f;
                            Cf[base] = v + r;
                        }
                    } else if (mode == 1) {
                        Ch[(long long)row * ldc + c] = __float2half_rn(v);
                    } else {
                        // QKV routing: c<64 -> q, c<128 -> k, else -> vT (SEQ compile-time)
                        __half hv = __float2half_rn(v);
                        if (c < 64) {
                            Ch[(long long)row * DIM + head * DH + c] = hv;
                        } else if (c < 128) {
                            Kout[(long long)row * DIM + head * DH + (c - 64)] = hv;
                        } else {
                            int nb = row / SEQ, s = row - nb * SEQ;
                            Vout[((long long)(nb * NHEAD + head) * DH + (c - 128)) * ALD + s] = hv;
                        }
                    }
                }
            }
        }
    }
}

// ======================================================================
//  fused flash attention: per (qtile, h, n) CTA
// ======================================================================
#define FA_RSQ 144
#define FA_RSV 464
#define FA_SM_Q 0
#define FA_SM_K (128 * FA_RSQ)
#define FA_SM_V (FA_SM_K + ALD * FA_RSQ)
#define FA_SMEM (FA_SM_V + DH * FA_RSV)

__global__ __launch_bounds__(256, 1)
void flash_kernel(const __half* __restrict__ qh, const __half* __restrict__ kh,
                  const __half* __restrict__ vth, float* __restrict__ outb)
{
    extern __shared__ char sm[];
    uint32_t smb = smem_u32(sm);
    const int tid = threadIdx.x;
    const int lid = tid & 31;
    const int wid = tid >> 5;
    const int q0 = blockIdx.x * 128;
    const int h  = blockIdx.y;
    const int n  = blockIdx.z;
    const int wr = wid * 16;

    const long long qbase = ((long long)n * SEQ) * DIM + h * DH;
    const long long vbase = ((long long)n * NHEAD + h) * (long long)DH * ALD;

    #pragma unroll
    for (int t = 0; t < 4; t++) {
        int id = tid + t * 256;
        int row = id >> 3, ch = id & 7;
        int s = q0 + row; if (s >= SEQ) s = SEQ - 1;
        *(uint4*)(sm + FA_SM_Q + row * FA_RSQ + ch * 16) =
            *(const uint4*)(qh + qbase + (long long)s * DIM + ch * 8);
    }
    #pragma unroll
    for (int t = 0; t < 7; t++) {
        int id = tid + t * 256;
        int row = id >> 3, ch = id & 7;
        int s = row; if (s >= SEQ) s = SEQ - 1;
        *(uint4*)(sm + FA_SM_K + row * FA_RSQ + ch * 16) =
            *(const uint4*)(kh + qbase + (long long)s * DIM + ch * 8);
    }
    for (int id = tid; id < DH * 28; id += 256) {
        int row = id / 28, ch = id % 28;
        *(uint4*)(sm + FA_SM_V + row * FA_RSV + ch * 16) =
            *(const uint4*)(vth + vbase + (long long)row * ALD + ch * 8);
    }
    __syncthreads();

    uint32_t aq[4][4];
    #pragma unroll
    for (int kt = 0; kt < 4; kt++) {
        uint32_t row = wr + ((lid >> 3) & 1) * 8 + (lid & 7);
        uint32_t koff = kt * 16 + (lid >> 4) * 8;
        ldm4(aq[kt], smb + FA_SM_Q + row * FA_RSQ + koff * 2);
    }
    float acc[28][4];
    #pragma unroll
    for (int j = 0; j < 28; j++)
        #pragma unroll
        for (int r = 0; r < 4; r++) acc[j][r] = 0.f;

    #pragma unroll
    for (int nt = 0; nt < 14; nt++) {
        #pragma unroll
        for (int kt = 0; kt < 4; kt++) {
            uint32_t bk[4];
            uint32_t row = nt * 16 + (lid >> 4) * 8 + (lid & 7);
            uint32_t koff = kt * 16 + ((lid >> 3) & 1) * 8;
            ldm4(bk, smb + FA_SM_K + row * FA_RSQ + koff * 2);
            mma_fp16(acc[nt * 2],     aq[kt], bk[0], bk[1]);
            mma_fp16(acc[nt * 2 + 1], aq[kt], bk[2], bk[3]);
        }
    }

    float m0 = -1e30f, m1 = -1e30f;
    #pragma unroll
    for (int j = 0; j < 28; j++) {
        int c0 = j * 8 + (lid & 3) * 2;
        if (c0 >= SEQ)     { acc[j][0] = -1e30f; acc[j][2] = -1e30f; }
        if (c0 + 1 >= SEQ) { acc[j][1] = -1e30f; acc[j][3] = -1e30f; }
        m0 = fmaxf(m0, fmaxf(acc[j][0], acc[j][1]));
        m1 = fmaxf(m1, fmaxf(acc[j][2], acc[j][3]));
    }
    m0 = fmaxf(m0, __shfl_xor_sync(0xffffffffu, m0, 1));
    m0 = fmaxf(m0, __shfl_xor_sync(0xffffffffu, m0, 2));
    m1 = fmaxf(m1, __shfl_xor_sync(0xffffffffu, m1, 1));
    m1 = fmaxf(m1, __shfl_xor_sync(0xffffffffu, m1, 2));

    float s0 = 0.f, s1 = 0.f;
    #pragma unroll
    for (int j = 0; j < 28; j++) {
        acc[j][0] = __expf((acc[j][0] - m0) * 0.125f);
        acc[j][1] = __expf((acc[j][1] - m0) * 0.125f);
        acc[j][2] = __expf((acc[j][2] - m1) * 0.125f);
        acc[j][3] = __expf((acc[j][3] - m1) * 0.125f);
        s0 += acc[j][0] + acc[j][1];
        s1 += acc[j][2] + acc[j][3];
    }
    s0 += __shfl_xor_sync(0xffffffffu, s0, 1);
    s0 += __shfl_xor_sync(0xffffffffu, s0, 2);
    s1 += __shfl_xor_sync(0xffffffffu, s1, 1);
    s1 += __shfl_xor_sync(0xffffffffu, s1, 2);
    float inv0 = 1.0f / s0, inv1 = 1.0f / s1;

    float o[8][4];
    #pragma unroll
    for (int g = 0; g < 8; g++)
        #pragma unroll
        for (int r = 0; r < 4; r++) o[g][r] = 0.f;

    #pragma unroll
    for (int kt2 = 0; kt2 < 14; kt2++) {
        int j0 = kt2 * 2, j1 = j0 + 1;
        uint32_t af[4];
        af[0] = pack_h2(acc[j0][0], acc[j0][1]);
        af[1] = pack_h2(acc[j0][2], acc[j0][3]);
        af[2] = pack_h2(acc[j1][0], acc[j1][1]);
        af[3] = pack_h2(acc[j1][2], acc[j1][3]);
        #pragma unroll
        for (int g = 0; g < 4; g++) {
            uint32_t bv[4];
            uint32_t row = g * 16 + (lid >> 4) * 8 + (lid & 7);
            uint32_t koff = kt2 * 16 + ((lid >> 3) & 1) * 8;
            ldm4(bv, smb + FA_SM_V + row * FA_RSV + koff * 2);
            mma_fp16(o[g * 2],     af, bv[0], bv[1]);
            mma_fp16(o[g * 2 + 1], af, bv[2], bv[3]);
        }
    }

    int r0 = q0 + wr + (lid >> 2);
    int r1 = r0 + 8;
    #pragma unroll
    for (int g = 0; g < 8; g++) {
        int c = h * DH + g * 8 + (lid & 3) * 2;
        if (r0 < SEQ) {
            long long b = ((long long)n * SEQ + r0) * DIM + c;
            outb[b]     += o[g][0] * inv0;
            outb[b + 1] += o[g][1] * inv0;
        }
        if (r1 < SEQ) {
            long long b = ((long long)n * SEQ + r1) * DIM + c;
            outb[b]     += o[g][2] * inv1;
            outb[b + 1] += o[g][3] * inv1;
        }
    }
}

// ======================================================================
//  small kernels
// ======================================================================
__global__ void zero_fp16_kernel(__half* __restrict__ p, long long n) {
    long long i = ((long long)blockIdx.x * 256 + threadIdx.x) * 8;
    if (i >= n) return;
    *(uint4*)(p + i) = make_uint4(0, 0, 0, 0);
}

// fp32 -> fp16, 8 elements per thread
__global__ void cvt_kernel(const float* __restrict__ x, __half* __restrict__ h, long long n) {
    long long i = ((long long)blockIdx.x * 256 + threadIdx.x) * 8;
    if (i >= n) return;
    float4 a = *(const float4*)(x + i);
    float4 b = *(const float4*)(x + i + 4);
    uint4 o;
    o.x = pack_h2(a.x, a.y);
    o.y = pack_h2(a.z, a.w);
    o.z = pack_h2(b.x, b.y);
    o.w = pack_h2(b.z, b.w);
    *(uint4*)(h + i) = o;
}

// pack Wq/Wk/Wv [L][H][64][64] fp32 -> wqkv [L][H][192][64] fp16
__global__ void pack_qkv_w_kernel(const float* __restrict__ Wq, const float* __restrict__ Wk,
                                  const float* __restrict__ Wv, __half* __restrict__ out) {
    long long idx = (long long)blockIdx.x * 256 + threadIdx.x;
    const long long total = (long long)NLAYER * NHEAD * 192 * DH;
    if (idx >= total) return;
    int c = (int)(idx & 63);
    long long t = idx >> 6;
    int r = (int)(t % 192);
    long long lh = t / 192;
    const float* src = (r < 64) ? Wq : (r < 128 ? Wk : Wv);
    int rr = r & 63;
    out[idx] = __float2half_rn(src[(lh * 64 + rr) * 64 + c]);
}

// pack bq/bk/bv [L][H][64] fp32 -> bqkv [L][H][192] fp32
__global__ void pack_qkv_b_kernel(const float* __restrict__ bq, const float* __restrict__ bk,
                                  const float* __restrict__ bv, float* __restrict__ out) {
    long long idx = (long long)blockIdx.x * 256 + threadIdx.x;
    const long long total = (long long)NLAYER * NHEAD * 192;
    if (idx >= total) return;
    int r = (int)(idx % 192);
    long long lh = idx / 192;
    const float* src = (r < 64) ? bq : (r < 128 ? bk : bv);
    out[idx] = src[lh * 64 + (r & 63)];
}

__global__ void patchify_kernel(const float* __restrict__ x, __half* __restrict__ ph) {
    long long idx = (long long)blockIdx.x * 256 + threadIdx.x;
    const long long total = (long long)BATCH * NPATCH * DIM;
    if (idx >= total) return;
    int e = (int)(idx % DIM);
    long long r = idx / DIM;
    int p = (int)(r % NPATCH);
    int n = (int)(r / NPATCH);
    int c = e / 256;
    int hw = e % 256;
    int hi = hw / 16, wi = hw % 16;
    int pi = p / 14, pj = p % 14;
    ph[idx] = __float2half_rn(
        x[(((long long)n * 3 + c) * 224 + (pi * 16 + hi)) * 224 + (pj * 16 + wi)]);
}

__global__ void assemble_kernel(const float* __restrict__ tmp, const float* __restrict__ cls,
                                float* __restrict__ out) {
    long long idx = (long long)blockIdx.x * 256 + threadIdx.x;
    const long long total = (long long)BATCH * SEQ * DIM;
    if (idx >= total) return;
    int d = (int)(idx % DIM);
    long long r = idx / DIM;
    int s = (int)(r % SEQ);
    int n = (int)(r / SEQ);
    float v = (s == 0) ? cls[d] : tmp[((long long)n * NPATCH + (s - 1)) * DIM + d];
    float pe;
    if ((s & 1) == 0) pe = sinf((float)s / powf(10000.0f, (float)d / (float)DIM));
    else              pe = cosf((float)s / powf(10000.0f, (float)(d - 1) / (float)DIM));
    out[idx] = v + pe;
}

// warp-per-row layernorm: 8 rows per 256-thread block, shuffle-only reduction
__global__ __launch_bounds__(256)
void layernorm_kernel(const float* __restrict__ x, const float* __restrict__ g,
                      const float* __restrict__ b, __half* __restrict__ yh) {
    int warp = threadIdx.x >> 5;
    int lid = threadIdx.x & 31;
    long long row = (long long)blockIdx.x * 8 + warp;
    const float4* p = (const float4*)(x + row * DIM);
    const float4* gv = (const float4*)g;
    const float4* bv = (const float4*)b;

    float4 v[6];
    float s = 0.f, s2 = 0.f;
    #pragma unroll
    for (int k = 0; k < 6; k++) {
        v[k] = p[lid + k * 32];
        s  += v[k].x + v[k].y + v[k].z + v[k].w;
        s2 += v[k].x * v[k].x + v[k].y * v[k].y + v[k].z * v[k].z + v[k].w * v[k].w;
    }
    #pragma unroll
    for (int o = 16; o > 0; o >>= 1) {
        s  += __shfl_xor_sync(0xffffffffu, s, o);
        s2 += __shfl_xor_sync(0xffffffffu, s2, o);
    }
    float mu = s * (1.0f / DIM);
    float var = s2 * (1.0f / DIM) - mu * mu;
    float inv = rsqrtf(var + 1e-5f);

    uint2* out = (uint2*)(yh + row * DIM);
    #pragma unroll
    for (int k = 0; k < 6; k++) {
        float4 gg = gv[lid + k * 32];
        float4 bb = bv[lid + k * 32];
        float r0 = (v[k].x - mu) * inv * gg.x + bb.x;
        float r1 = (v[k].y - mu) * inv * gg.y + bb.y;
        float r2 = (v[k].z - mu) * inv * gg.z + bb.z;
        float r3 = (v[k].w - mu) * inv * gg.w + bb.w;
        uint2 o;
        o.x = pack_h2(r0, r1);
        o.y = pack_h2(r2, r3);
        out[lid + k * 32] = o;
    }
}

// ======================================================================
//  generic SIMT GEMM (head only)
// ======================================================================
#define BM 64
#define BN 64
#define BK 16

__global__ void gemm_simt_kernel(
    const float* __restrict__ A, int lda,
    const float* __restrict__ B, int ldb,
    float* __restrict__ C, int ldc,
    const float* __restrict__ bias,
    int M, int N, int K)
{
    __shared__ float As[BK][BM];
    __shared__ float Bs[BK][BN];
    int bm = blockIdx.y * BM;
    int bn = blockIdx.x * BN;
    int tid = threadIdx.x;
    int tx = tid % 16, ty = tid / 16;
    float acc[4][4] = {};
    for (int k0 = 0; k0 < K; k0 += BK) {
        #pragma unroll
        for (int i = 0; i < 4; i++) {
            int idx = tid + i * 256;
            int m = idx / BK, kk = idx % BK;
            int gm = bm + m, gk = k0 + kk;
            As[kk][m] = (gm < M && gk < K) ? A[(long long)gm * lda + gk] : 0.f;
        }
        #pragma unroll
        for (int i = 0; i < 4; i++) {
            int idx = tid + i * 256;
            int n = idx / BK, kk = idx % BK;
            int gn = bn + n, gk = k0 + kk;
            Bs[kk][n] = (gn < N && gk < K) ? B[(long long)gn * ldb + gk] : 0.f;
        }
        __syncthreads();
        #pragma unroll
        for (int kk = 0; kk < BK; kk++) {
            float a[4], b[4];
            #pragma unroll
            for (int i = 0; i < 4; i++) a[i] = As[kk][ty * 4 + i];
            #pragma unroll
            for (int j = 0; j < 4; j++) b[j] = Bs[kk][tx * 4 + j];
            #pragma unroll
            for (int i = 0; i < 4; i++)
                #pragma unroll
                for (int j = 0; j < 4; j++)
                    acc[i][j] += a[i] * b[j];
        }
        __syncthreads();
    }
    #pragma unroll
    for (int i = 0; i < 4; i++) {
        int gm = bm + ty * 4 + i;
        if (gm >= M) continue;
        #pragma unroll
        for (int j = 0; j < 4; j++) {
            int gn = bn + tx * 4 + j;
            if (gn >= N) continue;
            C[(long long)gm * ldc + gn] = acc[i][j] + (bias ? bias[gn] : 0.f);
        }
    }
}

// ======================================================================
//  launch helper
// ======================================================================
struct MArgs {
    const __half *Ah; long long lda, sA1, sA2;
    const __half *Bh; long long ldb, sB1, sB2;
    float* Cf; __half* Ch; long long ldc, sC1, sC2;
    const float* bias; long long sb1, sb2;
    const float* R;
    __half *Kout, *Vout;
    int M, N, K; int gelu; int z2; int Z; int mode; int ksplit;
};

static void launch_mma(const MArgs& a, cudaStream_t stream) {
    static bool attr_set = false;
    if (!attr_set) {
        cudaFuncSetAttribute(gemm_fp16_kernel,
                             cudaFuncAttributeMaxDynamicSharedMemorySize, SMEM_MMA);
        cudaFuncSetAttribute(flash_kernel,
                             cudaFuncAttributeMaxDynamicSharedMemorySize, FA_SMEM);
        attr_set = true;
    }
    int zdim = (a.ksplit > 1) ? a.ksplit : a.Z;
    dim3 grid((a.N + 127) / 128, (a.M + 127) / 128, zdim);
    gemm_fp16_kernel<<<grid, 256, SMEM_MMA, stream>>>(
        a.Ah, a.lda, a.sA1, a.sA2,
        a.Bh, a.ldb, a.sB1, a.sB2,
        a.Cf, a.Ch, a.ldc, a.sC1, a.sC2,
        a.bias, a.sb1, a.sb2, a.R, a.Kout, a.Vout,
        a.M, a.N, a.K, a.gelu, a.z2, a.mode, SEQ, a.ksplit);
}

// ======================================================================
//  orchestration (single stream)
// ======================================================================
extern "C" void kernel_launch(void* const* d_in, const int* in_sizes, int n_in,
                              void* d_out, int out_size) {
    (void)in_sizes; (void)n_in; (void)out_size;
    const float* x    = (const float*)d_in[0];
    const float* Wp   = (const float*)d_in[1];
    const float* bp   = (const float*)d_in[2];
    const float* cls  = (const float*)d_in[3];
    const float* ln1g = (const float*)d_in[4];
    const float* ln1b = (const float*)d_in[5];
    const float* Wq   = (const float*)d_in[6];
    const float* bq   = (const float*)d_in[7];
    const float* Wk   = (const float*)d_in[8];
    const float* bk   = (const float*)d_in[9];
    const float* Wv   = (const float*)d_in[10];
    const float* bv   = (const float*)d_in[11];
    const float* ln2g = (const float*)d_in[12];
    const float* ln2b = (const float*)d_in[13];
    const float* W1   = (const float*)d_in[14];
    const float* b1   = (const float*)d_in[15];
    const float* W2   = (const float*)d_in[16];
    const float* b2   = (const float*)d_in[17];
    const float* Wh   = (const float*)d_in[18];
    const float* bh   = (const float*)d_in[19];
    float* out_final  = (float*)d_out;

    float *outb, *ptmp, *bqkv;
    __half *ph, *xh, *mh, *qh, *kh, *vth;
    __half *wph, *w1h, *w2h, *wqkv;
    cudaGetSymbolAddress((void**)&outb, g_out);
    cudaGetSymbolAddress((void**)&ptmp, g_ptmp);
    cudaGetSymbolAddress((void**)&ph,   g_ph);
    cudaGetSymbolAddress((void**)&xh,   g_xh);
    cudaGetSymbolAddress((void**)&mh,   g_mh);
    cudaGetSymbolAddress((void**)&qh,   g_qh);
    cudaGetSymbolAddress((void**)&kh,   g_kh);
    cudaGetSymbolAddress((void**)&vth,  g_vth);
    cudaGetSymbolAddress((void**)&wph,  g_wph);
    cudaGetSymbolAddress((void**)&w1h,  g_w1h);
    cudaGetSymbolAddress((void**)&w2h,  g_w2h);
    cudaGetSymbolAddress((void**)&wqkv, g_wqkv);
    cudaGetSymbolAddress((void**)&bqkv, g_bqkv);

    cudaStream_t stream = 0;
    const int ROWS = BATCH * SEQ;                    // 12608

    // 0) weight converts + QKV pack + vT pad zero
    {
        long long n;
        n = (long long)DIM * DIM;
        cvt_kernel<<<(unsigned)((n / 8 + 255) / 256), 256, 0, stream>>>(Wp, wph, n);
        n = (long long)NLAYER * MLPD * DIM;
        cvt_kernel<<<(unsigned)((n / 8 + 255) / 256), 256, 0, stream>>>(W1, w1h, n);
        cvt_kernel<<<(unsigned)((n / 8 + 255) / 256), 256, 0, stream>>>(W2, w2h, n);
        n = (long long)NLAYER * NHEAD * 192 * DH;
        pack_qkv_w_kernel<<<(unsigned)((n + 255) / 256), 256, 0, stream>>>(Wq, Wk, Wv, wqkv);
        n = (long long)NLAYER * NHEAD * 192;
        pack_qkv_b_kernel<<<(unsigned)((n + 255) / 256), 256, 0, stream>>>(bq, bk, bv, bqkv);
        n = (long long)BATCH * NHEAD * DH * ALD;
        zero_fp16_kernel<<<(unsigned)((n / 8 + 255) / 256), 256, 0, stream>>>(vth, n);
    }

    // 1) patchify -> fp16
    {
        long long total = (long long)BATCH * NPATCH * DIM;
        patchify_kernel<<<(unsigned)((total + 255) / 256), 256, 0, stream>>>(x, ph);
    }
    // 2) patch embedding: ptmp = patches @ Wp^T + bp
    {
        MArgs a = {};
        a.Ah = ph; a.lda = DIM;
        a.Bh = wph; a.ldb = DIM;
        a.Cf = ptmp; a.ldc = DIM;
        a.bias = bp;
        a.M = BATCH * NPATCH; a.N = DIM; a.K = DIM;
        a.z2 = 1; a.Z = 1; a.mode = 0; a.ksplit = 1;
        launch_mma(a, stream);
    }
    // 3) assemble tokens + cls + positional embedding
    {
        long long total = (long long)BATCH * SEQ * DIM;
        assemble_kernel<<<(unsigned)((total + 255) / 256), 256, 0, stream>>>(ptmp, cls, outb);
    }

    for (int l = 0; l < NLAYER; l++) {
        // --- ln1 -> fp16 ---
        layernorm_kernel<<<ROWS / 8, 256, 0, stream>>>(outb, ln1g + l * DIM, ln1b + l * DIM, xh);

        // --- fused QKV projection (one launch, Z=12 heads, N=192) ---
        {
            MArgs a = {};
            a.Ah = xh; a.lda = DIM; a.sA2 = DH;
            a.Bh = wqkv + (long long)l * NHEAD * 192 * DH; a.ldb = DH; a.sB2 = 192 * DH;
            a.Ch = qh; a.Kout = kh; a.Vout = vth;
            a.bias = bqkv + (long long)l * NHEAD * 192; a.sb2 = 192;
            a.M = ROWS; a.N = 192; a.K = DH;
            a.z2 = NHEAD; a.Z = NHEAD; a.mode = 2; a.ksplit = 1;
            launch_mma(a, stream);
        }

        // --- fused attention + residual ---
        {
            dim3 grid(2, NHEAD, BATCH);
            flash_kernel<<<grid, 256, FA_SMEM, stream>>>(qh, kh, vth, outb);
        }

        // --- ln2 -> fp16 ---
        layernorm_kernel<<<ROWS / 8, 256, 0, stream>>>(outb, ln2g + l * DIM, ln2b + l * DIM, xh);

        // --- MLP1 + GELU -> fp16 ---
        {
            MArgs a = {};
            a.Ah = xh; a.lda = DIM;
            a.Bh = w1h + (long long)l * MLPD * DIM; a.ldb = DIM;
            a.Ch = mh; a.ldc = MLPD;
            a.bias = b1 + (long long)l * MLPD;
            a.M = ROWS; a.N = MLPD; a.K = DIM; a.gelu = 1;
            a.z2 = 1; a.Z = 1; a.mode = 1; a.ksplit = 1;
            launch_mma(a, stream);
        }
        // --- MLP2 + residual -> fp32, split-K=2 (atomicAdd onto outb) ---
        {
            MArgs a = {};
            a.Ah = mh; a.lda = MLPD;
            a.Bh = w2h + (long long)l * DIM * MLPD; a.ldb = MLPD;
            a.Cf = outb; a.ldc = DIM;
            a.bias = b2 + (long long)l * DIM;
            a.M = ROWS; a.N = DIM; a.K = MLPD;
            a.z2 = 1; a.Z = 1; a.mode = 0; a.ksplit = 2;
            launch_mma(a, stream);
        }
    }

    // --- head: out_final = out[:,0,:] @ Wh^T + bh (SIMT, tiny) ---
    {
        dim3 grid((OUTD + BN - 1) / BN, (BATCH + BM - 1) / BM, 1);
        gemm_simt_kernel<<<grid, 256, 0, stream>>>(
            outb, (int)((long long)SEQ * DIM), Wh, DIM, out_final, OUTD, bh, BATCH, OUTD, DIM);
    }
}